// round 13
// baseline (speedup 1.0000x reference)
#include <cuda_runtime.h>
#include <cuda_bf16.h>
#include <cstdint>

// ---------------------------------------------------------------------------
// Problem constants: B=8, NT=32, NO=8, C=512, VD=1024, RD=300, H=4
// ---------------------------------------------------------------------------
#define B_  8
#define C_  512
#define H_  4
#define DH_ 128
#define SEGS 2048
#define TOK  16384
#define ROWS_O 4096
#define OUT_ROWS 4096

// ---------------------------------------------------------------------------
// fp32 scratch
// ---------------------------------------------------------------------------
__device__ float g_T1 [ROWS_O * 1024];
__device__ float g_T2 [ROWS_O * 512];
__device__ float g_T4 [TOK * 512];
__device__ float g_QKV[TOK * 1536];
__device__ float g_bqkv[1536];

// bf16 hi/lo plane scratch
__device__ __nv_bfloat16 pAo_h [8*512*512],    pAo_l [8*512*512];
__device__ __nv_bfloat16 pAr_h [8*2048*2048],  pAr_l [8*2048*2048];
__device__ __nv_bfloat16 pSo_h [4096*1024],    pSo_l [4096*1024];
__device__ __nv_bfloat16 pSr_h [16384*304],    pSr_l [16384*304];   // ld=304
__device__ __nv_bfloat16 pWo1_h[1024*1024],    pWo1_l[1024*1024];
__device__ __nv_bfloat16 pWo2_h[1024*512],     pWo2_l[1024*512];
__device__ __nv_bfloat16 pWr1_h[300*1024],     pWr1_l[300*1024];
__device__ __nv_bfloat16 pWr2_h[1024*512],     pWr2_l[1024*512];
__device__ __nv_bfloat16 pWqkv_h[512*1536],    pWqkv_l[512*1536];
__device__ __nv_bfloat16 pWp_h [512*512],      pWp_l [512*512];
__device__ __nv_bfloat16 pWe_h [1024*512],     pWe_l [1024*512];
__device__ __nv_bfloat16 pT1_h [4096*1024],    pT1_l [4096*1024];
__device__ __nv_bfloat16 pH1o_h[4096*1024],    pH1o_l[4096*1024];
__device__ __nv_bfloat16 pT2_h [4096*512],     pT2_l [4096*512];
__device__ __nv_bfloat16 pZ_h  [16384*304],    pZ_l  [16384*304];   // ld=304
__device__ __nv_bfloat16 pH1r_h[16384*1024],   pH1r_l[16384*1024];
__device__ __nv_bfloat16 pT4_h [16384*512],    pT4_l [16384*512];
__device__ __nv_bfloat16 pGr_h [16384*512],    pGr_l [16384*512];
__device__ __nv_bfloat16 pOm_h [4096*512],     pOm_l [4096*512];
__device__ __nv_bfloat16 pCat_h[4096*1024],    pCat_l[4096*1024];

// ---------------------------------------------------------------------------
// helpers
// ---------------------------------------------------------------------------
__device__ __forceinline__ uint32_t smem_u32(const void* p) {
    uint32_t a;
    asm("{ .reg .u64 t; cvta.to.shared.u64 t, %1; cvt.u32.u64 %0, t; }"
        : "=r"(a) : "l"(p));
    return a;
}
__device__ __forceinline__ void cp16(uint32_t dst, const void* src, int sz) {
    asm volatile("cp.async.cg.shared.global [%0], [%1], 16, %2;"
                 :: "r"(dst), "l"(src), "r"(sz));
}
__device__ __forceinline__ void cp_commit() {
    asm volatile("cp.async.commit_group;");
}
__device__ __forceinline__ void cp_wait(int pend) {
    if (pend >= 1) asm volatile("cp.async.wait_group 1;");
    else           asm volatile("cp.async.wait_group 0;");
}
__device__ __forceinline__ void ldsm4(uint32_t* r, uint32_t addr) {
    asm volatile("ldmatrix.sync.aligned.m8n8.x4.shared.b16 {%0,%1,%2,%3}, [%4];"
                 : "=r"(r[0]), "=r"(r[1]), "=r"(r[2]), "=r"(r[3]) : "r"(addr));
}
__device__ __forceinline__ void ldsm4t(uint32_t* r, uint32_t addr) {
    asm volatile("ldmatrix.sync.aligned.m8n8.x4.trans.shared.b16 {%0,%1,%2,%3}, [%4];"
                 : "=r"(r[0]), "=r"(r[1]), "=r"(r[2]), "=r"(r[3]) : "r"(addr));
}
__device__ __forceinline__ void mma16816(float* d, const uint32_t* a, const uint32_t* b) {
    asm volatile(
        "mma.sync.aligned.m16n8k16.row.col.f32.bf16.bf16.f32 "
        "{%0,%1,%2,%3}, {%4,%5,%6,%7}, {%8,%9}, {%0,%1,%2,%3};"
        : "+f"(d[0]), "+f"(d[1]), "+f"(d[2]), "+f"(d[3])
        : "r"(a[0]), "r"(a[1]), "r"(a[2]), "r"(a[3]), "r"(b[0]), "r"(b[1]));
}
__device__ __forceinline__ void split1(float x, __nv_bfloat16& h, __nv_bfloat16& l) {
    h = __float2bfloat16(x);
    l = __float2bfloat16(x - __bfloat162float(h));
}

// ---------------------------------------------------------------------------
// SMEM stage layout (bytes)
// ---------------------------------------------------------------------------
#define PITCH_A 80
#define PITCH_B 272
#define OFF_AL 10240
#define OFF_BH 20480
#define OFF_BL 29184
#define STAGE_B 37888
#define NSTAGE 3
#define SMEM_DYN (NSTAGE * STAGE_B)     // 113664 -> 2 CTAs/SM

// ---------------------------------------------------------------------------
// GEMM descriptor (passed by value; two per launch -> merged grids)
// ---------------------------------------------------------------------------
struct GDesc {
    const __nv_bfloat16 *Ah, *Al, *Bh, *Bl;
    const float *bias, *X;
    float* Cf;
    __nv_bfloat16 *Ch, *Cl;
    long sAp, sBp, sX, sCf, sCo;
    int lda, ldb, ldo;
    int M, N, K, relu, rowmap;
    int gx, gy;
};

// ---------------------------------------------------------------------------
// HMMA bf16-split GEMM v6: 256 threads (8 warps, 64x32 warp tile),
// 128x128 CTA tile, 3-stage cp.async pipeline, forced 2 CTAs/SM
// => 4 warps/SMSP from 2 independent CTAs (latency hiding).
// ---------------------------------------------------------------------------
__global__ __launch_bounds__(256, 2)
void mm2_kernel(GDesc d0, GDesc d1, int boundary)
{
    extern __shared__ char smem[];
    const uint32_t sbase = smem_u32(smem);

    const bool second = ((int)blockIdx.x >= boundary);
    const GDesc& d = second ? d1 : d0;
    const int local = (int)blockIdx.x - (second ? boundary : 0);
    const int gxy = d.gx * d.gy;
    const int bz  = local / gxy;
    const int rem = local - bz * gxy;
    const int by  = rem / d.gx;
    const int bxx = rem - by * d.gx;

    const __nv_bfloat16* Ah = d.Ah + (long)bz * d.sAp;
    const __nv_bfloat16* Al = d.Al + (long)bz * d.sAp;
    const __nv_bfloat16* Bh = d.Bh + (long)bz * d.sBp;
    const __nv_bfloat16* Bl = d.Bl + (long)bz * d.sBp;
    float* Cf = d.Cf ? (d.Cf + (long)bz * d.sCf) : nullptr;
    __nv_bfloat16* Ch = d.Ch ? (d.Ch + (long)bz * d.sCo) : nullptr;
    __nv_bfloat16* Cl = d.Cl ? (d.Cl + (long)bz * d.sCo) : nullptr;
    const float* X = d.X ? (d.X + (long)bz * d.sX) : nullptr;
    const int lda = d.lda, ldb = d.ldb, N = d.N, K = d.K;

    const int tid  = threadIdx.x;        // 0..255
    const int wid  = tid >> 5;           // 0..7
    const int lane = tid & 31;
    const int row0 = by * 128;
    const int col0 = bxx * 128;
    const int wm = wid >> 2;             // 0..1 -> rows wm*64
    const int wn = wid & 3;              // 0..3 -> cols wn*32

    float acc[4][4][4];
    #pragma unroll
    for (int mt = 0; mt < 4; ++mt)
        #pragma unroll
        for (int nt = 0; nt < 4; ++nt)
            #pragma unroll
            for (int e = 0; e < 4; ++e) acc[mt][nt][e] = 0.f;

    const int nch = (K + 31) >> 5;

    auto issueStage = [&](int c, int buf) {
        const int k0 = c << 5;
        const uint32_t sb = sbase + buf * STAGE_B;
        #pragma unroll
        for (int i = 0; i < 2; ++i) {
            const int ch  = tid + i * 256;
            const int row = ch >> 2;
            const int o8  = (ch & 3) * 8;
            const int rem2 = K - (k0 + o8);
            const int sz  = rem2 >= 8 ? 16 : (rem2 > 0 ? rem2 * 2 : 0);
            const long so = (long)(row0 + row) * lda + (sz ? (k0 + o8) : 0);
            const uint32_t dst = sb + row * PITCH_A + (ch & 3) * 16;
            cp16(dst,          Ah + so, sz);
            cp16(dst + OFF_AL, Al + so, sz);
        }
        #pragma unroll
        for (int i = 0; i < 2; ++i) {
            const int ch   = tid + i * 256;
            const int krow = ch >> 4;
            const int no8  = (ch & 15) * 8;
            const int remn = N - (col0 + no8);
            int sz = (k0 + krow < K) ? (remn >= 8 ? 16 : (remn > 0 ? remn * 2 : 0)) : 0;
            const long so = sz ? ((long)(k0 + krow) * ldb + col0 + no8) : 0;
            const uint32_t dst = sb + OFF_BH + krow * PITCH_B + (ch & 15) * 16;
            cp16(dst,                     Bh + so, sz);
            cp16(dst + (OFF_BL - OFF_BH), Bl + so, sz);
        }
    };

    auto computeChunk = [&](int buf) {
        const uint32_t sb = sbase + buf * STAGE_B;
        #pragma unroll
        for (int kb = 0; kb < 32; kb += 16) {
            // B fragments for 32-col warp tile: 2 ldsm4t pairs per plane
            uint32_t bhf[4][2], blf[4][2];
            #pragma unroll
            for (int pair = 0; pair < 2; ++pair) {
                const uint32_t krow = kb + ((lane >> 3) & 1) * 8 + (lane & 7);
                const uint32_t ncol = wn * 32 + pair * 16 + (lane >> 4) * 8;
                const uint32_t boff = sb + OFF_BH + krow * PITCH_B + ncol * 2;
                uint32_t r4[4];
                ldsm4t(r4, boff);
                bhf[pair * 2][0] = r4[0]; bhf[pair * 2][1] = r4[1];
                bhf[pair * 2 + 1][0] = r4[2]; bhf[pair * 2 + 1][1] = r4[3];
                ldsm4t(r4, boff + (OFF_BL - OFF_BH));
                blf[pair * 2][0] = r4[0]; blf[pair * 2][1] = r4[1];
                blf[pair * 2 + 1][0] = r4[2]; blf[pair * 2 + 1][1] = r4[3];
            }
            // A fragments per-mt (short liveness), 12 MMAs each
            #pragma unroll
            for (int mt = 0; mt < 4; ++mt) {
                uint32_t ahf[4], alf[4];
                const uint32_t arow = wm * 64 + mt * 16 + (lane & 15);
                const uint32_t aoff = sb + arow * PITCH_A + (kb + ((lane >> 4) * 8)) * 2;
                ldsm4(ahf, aoff);
                ldsm4(alf, aoff + OFF_AL);
                #pragma unroll
                for (int nt = 0; nt < 4; ++nt)
                    mma16816(acc[mt][nt], ahf, bhf[nt]);
                #pragma unroll
                for (int nt = 0; nt < 4; ++nt)
                    mma16816(acc[mt][nt], alf, bhf[nt]);
                #pragma unroll
                for (int nt = 0; nt < 4; ++nt)
                    mma16816(acc[mt][nt], ahf, blf[nt]);
            }
        }
    };

    issueStage(0, 0); cp_commit();
    if (nch > 1) { issueStage(1, 1); cp_commit(); }

    for (int c = 0; c < nch; ++c) {
        cp_wait((c + 2 <= nch) ? ((c + 1 < nch) ? 1 : 0) : 0);
        __syncthreads();
        if (c + 2 < nch) { issueStage(c + 2, (c + 2) % NSTAGE); cp_commit(); }
        computeChunk(c % NSTAGE);
    }

    // epilogue
    #pragma unroll
    for (int mt = 0; mt < 4; ++mt) {
        #pragma unroll
        for (int nt = 0; nt < 4; ++nt) {
            const int col = col0 + wn * 32 + nt * 8 + (lane & 3) * 2;
            if (col >= N) continue;
            #pragma unroll
            for (int half = 0; half < 2; ++half) {
                const int row = row0 + wm * 64 + mt * 16 + (lane >> 2) + half * 8;
                float2 v = make_float2(acc[mt][nt][half * 2], acc[mt][nt][half * 2 + 1]);
                if (d.bias) {
                    const float2 bv = *(const float2*)(d.bias + col);
                    v.x += bv.x; v.y += bv.y;
                }
                if (X) {
                    const float2 xv = *(const float2*)(X + (long)row * N + col);
                    v.x += xv.x; v.y += xv.y;
                }
                if (d.relu) { v.x = fmaxf(v.x, 0.f); v.y = fmaxf(v.y, 0.f); }
                int orow = row;
                if (d.rowmap) {
                    if (row < 2048) orow = ((row >> 3) << 4) + (row & 7);
                    else { const int a = row - 2048; orow = ((a >> 3) << 4) + 8 + (a & 7); }
                }
                if (Cf) *(float2*)(Cf + (long)orow * N + col) = v;
                if (Ch) {
                    __nv_bfloat16 hx, lx, hy, ly;
                    split1(v.x, hx, lx); split1(v.y, hy, ly);
                    const long o = (long)orow * d.ldo + col;
                    *(uint32_t*)(Ch + o) =
                        (uint32_t)__bfloat16_as_ushort(hx) | ((uint32_t)__bfloat16_as_ushort(hy) << 16);
                    *(uint32_t*)(Cl + o) =
                        (uint32_t)__bfloat16_as_ushort(lx) | ((uint32_t)__bfloat16_as_ushort(ly) << 16);
                }
            }
        }
    }
}

// ---------------------------------------------------------------------------
// Multi-job fp32 -> bf16 hi/lo plane convert (all inputs/weights, one launch)
// ---------------------------------------------------------------------------
#define NCVT 10
struct CvtJobs {
    const float* in[NCVT];
    __nv_bfloat16* h[NCVT];
    __nv_bfloat16* l[NCVT];
    long n[NCVT];
    int cols[NCVT], ldo[NCVT];
    int start[NCVT + 1];
};

__global__ __launch_bounds__(256)
void cvt_multi_kernel(CvtJobs J)
{
    const int bx = blockIdx.x;
    int j = 0;
    #pragma unroll
    for (int t = 0; t < NCVT - 1; ++t) if (bx >= J.start[t + 1]) j = t + 1;
    const long i = ((long)(bx - J.start[j]) * 256 + threadIdx.x) * 4;
    if (i >= J.n[j]) return;
    const float4 v = *(const float4*)(J.in[j] + i);
    long o;
    const int cols = J.cols[j], ldo = J.ldo[j];
    if (cols == ldo) o = i;
    else { const long r = i / cols; o = r * ldo + (int)(i - r * cols); }
    __nv_bfloat16 hh[4], ll[4];
    split1(v.x, hh[0], ll[0]); split1(v.y, hh[1], ll[1]);
    split1(v.z, hh[2], ll[2]); split1(v.w, hh[3], ll[3]);
    *(uint2*)(J.h[j] + o) = *(uint2*)hh;
    *(uint2*)(J.l[j] + o) = *(uint2*)ll;
}

__global__ __launch_bounds__(256)
void pack_qkv_kernel(const float* __restrict__ Wq, const float* __restrict__ Wk,
                     const float* __restrict__ Wv, const float* __restrict__ bq,
                     const float* __restrict__ bk, const float* __restrict__ bv,
                     __nv_bfloat16* __restrict__ h, __nv_bfloat16* __restrict__ l,
                     float* __restrict__ bias)
{
    const int idx = blockIdx.x * 256 + threadIdx.x;
    if (idx < 512 * 1536) {
        const int k = idx / 1536, n = idx % 1536, sel = n >> 9;
        const float* W = (sel == 0) ? Wq : (sel == 1) ? Wk : Wv;
        const float v = W[k * 512 + (n & 511)];
        __nv_bfloat16 hh, ll; split1(v, hh, ll);
        h[idx] = hh; l[idx] = ll;
    }
    if (idx < 1536) {
        const int sel = idx >> 9;
        const float* bb = (sel == 0) ? bq : (sel == 1) ? bk : bv;
        bias[idx] = bb[idx & 511];
    }
}

// ---------------------------------------------------------------------------
// Segmented MHA, both paths in one launch (blockIdx.z = path)
// ---------------------------------------------------------------------------
__global__ __launch_bounds__(128)
void attn_mean_kernel(const float* __restrict__ QKV,
                      __nv_bfloat16* __restrict__ OmH, __nv_bfloat16* __restrict__ OmL)
{
    const int s = blockIdx.x, h = blockIdx.y, path = blockIdx.z, tid = threadIdx.x;
    __shared__ float qs[8][DH_ + 1], ks[8][DH_ + 1], vs[8][DH_ + 1];
    __shared__ float sc[8][9], wj[8];

    #pragma unroll
    for (int i = 0; i < 8; ++i) {
        int g;
        if (path == 0) g = s * 8 + i;
        else { const int t = s >> 3, j = s & 7; g = t * 64 + i * 8 + j; }
        const long off = (long)g * 1536 + h * DH_ + tid;
        qs[i][tid] = QKV[off];
        ks[i][tid] = QKV[off + 512];
        vs[i][tid] = QKV[off + 1024];
    }
    __syncthreads();

    if (tid < 64) {
        const int i = tid >> 3, j = tid & 7;
        float d = 0.f;
        #pragma unroll 16
        for (int k = 0; k < DH_; ++k) d = fmaf(qs[i][k], ks[j][k], d);
        sc[i][j] = d * 0.08838834764831845f;
    }
    __syncthreads();
    if (tid < 8) {
        const int i = tid;
        float m = -1e30f;
        #pragma unroll
        for (int j = 0; j < 8; ++j) m = fmaxf(m, sc[i][j]);
        float e[8], sum = 0.f;
        #pragma unroll
        for (int j = 0; j < 8; ++j) { e[j] = __expf(sc[i][j] - m); sum += e[j]; }
        const float inv = 1.f / sum;
        #pragma unroll
        for (int j = 0; j < 8; ++j) sc[i][j] = e[j] * inv;
    }
    __syncthreads();
    if (tid < 8) {
        const int j = tid;
        float w = 0.f;
        #pragma unroll
        for (int i = 0; i < 8; ++i) w += sc[i][j];
        wj[j] = w * 0.125f;
    }
    __syncthreads();
    float o = 0.f;
    #pragma unroll
    for (int j = 0; j < 8; ++j) o = fmaf(wj[j], vs[j][tid], o);

    const long off = (long)(path * SEGS + s) * 512 + h * DH_ + tid;
    __nv_bfloat16 hh, ll; split1(o, hh, ll);
    OmH[off] = hh; OmL[off] = ll;
}

// ---------------------------------------------------------------------------
// Host
// ---------------------------------------------------------------------------
#define SYM(p, s) cudaGetSymbolAddress((void**)&p, s)

struct Planes { __nv_bfloat16 *h, *l; };

static GDesc mkDesc(Planes A, int lda, long sAp, Planes Bp, int ldb, long sBp,
                    const float* bias, const float* X, long sX,
                    float* Cf, long sCf, Planes Co, int ldo, long sCo,
                    int M, int N, int K, int nb, int relu, int rowmap,
                    int* ctas)
{
    GDesc d;
    d.Ah = A.h; d.Al = A.l; d.Bh = Bp.h; d.Bl = Bp.l;
    d.bias = bias; d.X = X; d.Cf = Cf; d.Ch = Co.h; d.Cl = Co.l;
    d.sAp = sAp; d.sBp = sBp; d.sX = sX; d.sCf = sCf; d.sCo = sCo;
    d.lda = lda; d.ldb = ldb; d.ldo = ldo;
    d.M = M; d.N = N; d.K = K; d.relu = relu; d.rowmap = rowmap;
    d.gx = (N + 127) / 128; d.gy = M / 128;
    *ctas = d.gx * d.gy * nb;
    return d;
}

static inline void launchPair(const GDesc& a, int ca, const GDesc& b, int cb)
{
    mm2_kernel<<<ca + cb, 256, SMEM_DYN>>>(a, b, ca);
}
static inline void launchOne(const GDesc& a, int ca)
{
    mm2_kernel<<<ca, 256, SMEM_DYN>>>(a, a, ca);
}

extern "C" void kernel_launch(void* const* d_in, const int* in_sizes, int n_in,
                              void* d_out, int out_size)
{
    const float* Ao   = (const float*)d_in[0];
    const float* srco = (const float*)d_in[1];
    const float* Ar   = (const float*)d_in[2];
    const float* srcr = (const float*)d_in[3];
    const float* Wo1  = (const float*)d_in[4];
    const float* Wo2  = (const float*)d_in[5];
    const float* Wr1  = (const float*)d_in[6];
    const float* Wr2  = (const float*)d_in[7];
    const float* Wq   = (const float*)d_in[8];
    const float* bq   = (const float*)d_in[9];
    const float* Wk   = (const float*)d_in[10];
    const float* bk   = (const float*)d_in[11];
    const float* Wv   = (const float*)d_in[12];
    const float* bv   = (const float*)d_in[13];
    const float* Wp   = (const float*)d_in[14];
    const float* bp   = (const float*)d_in[15];
    const float* We   = (const float*)d_in[16];
    const float* be   = (const float*)d_in[17];
    float* out = (float*)d_out;

    cudaFuncSetAttribute(mm2_kernel, cudaFuncAttributeMaxDynamicSharedMemorySize, SMEM_DYN);

    float *T1, *T2, *T4, *QKV, *bqkv;
    SYM(T1, g_T1); SYM(T2, g_T2); SYM(T4, g_T4);
    SYM(QKV, g_QKV); SYM(bqkv, g_bqkv);

    Planes PAo, PAr, PSo, PSr, PWo1, PWo2, PWr1, PWr2, PWqkv, PWp, PWe;
    Planes PT1, PH1o, PT2, PZ, PH1r, PT4, PGr, POm, PCat;
    SYM(PAo.h, pAo_h);   SYM(PAo.l, pAo_l);
    SYM(PAr.h, pAr_h);   SYM(PAr.l, pAr_l);
    SYM(PSo.h, pSo_h);   SYM(PSo.l, pSo_l);
    SYM(PSr.h, pSr_h);   SYM(PSr.l, pSr_l);
    SYM(PWo1.h, pWo1_h); SYM(PWo1.l, pWo1_l);
    SYM(PWo2.h, pWo2_h); SYM(PWo2.l, pWo2_l);
    SYM(PWr1.h, pWr1_h); SYM(PWr1.l, pWr1_l);
    SYM(PWr2.h, pWr2_h); SYM(PWr2.l, pWr2_l);
    SYM(PWqkv.h, pWqkv_h); SYM(PWqkv.l, pWqkv_l);
    SYM(PWp.h, pWp_h);   SYM(PWp.l, pWp_l);
    SYM(PWe.h, pWe_h);   SYM(PWe.l, pWe_l);
    SYM(PT1.h, pT1_h);   SYM(PT1.l, pT1_l);
    SYM(PH1o.h, pH1o_h); SYM(PH1o.l, pH1o_l);
    SYM(PT2.h, pT2_h);   SYM(PT2.l, pT2_l);
    SYM(PZ.h, pZ_h);     SYM(PZ.l, pZ_l);
    SYM(PH1r.h, pH1r_h); SYM(PH1r.l, pH1r_l);
    SYM(PT4.h, pT4_h);   SYM(PT4.l, pT4_l);
    SYM(PGr.h, pGr_h);   SYM(PGr.l, pGr_l);
    SYM(POm.h, pOm_h);   SYM(POm.l, pOm_l);
    SYM(PCat.h, pCat_h); SYM(PCat.l, pCat_l);

    const Planes NONE = {nullptr, nullptr};
    Planes PCatR = {PCat.h + 512, PCat.l + 512};   // right half of cat

    // ---- one merged conversion launch ----
    {
        CvtJobs J;
        const float* ins[NCVT] = {Ar, srcr, srco, Ao, Wo1, Wo2, Wr1, Wr2, Wp, We};
        Planes      ps [NCVT] = {PAr, PSr, PSo, PAo, PWo1, PWo2, PWr1, PWr2, PWp, PWe};
        long        ns [NCVT] = {(long)8*2048*2048, (long)16384*300, (long)4096*1024,
                                 (long)8*512*512, (long)1024*1024, (long)1024*512,
                                 (long)300*1024, (long)1024*512, (long)512*512,
                                 (long)1024*512};
        int         cs [NCVT] = {2048, 300, 1024, 512, 1024, 512, 1024, 512, 512, 512};
        int         ld [NCVT] = {2048, 304, 1024, 512, 1024, 512, 1024, 512, 512, 512};
        int cum = 0;
        for (int j = 0; j < NCVT; ++j) {
            J.in[j] = ins[j]; J.h[j] = ps[j].h; J.l[j] = ps[j].l;
            J.n[j] = ns[j]; J.cols[j] = cs[j]; J.ldo[j] = ld[j];
            J.start[j] = cum;
            cum += (int)((ns[j] + 1023) / 1024);
        }
        J.start[NCVT] = cum;
        cvt_multi_kernel<<<cum, 256>>>(J);
    }
    pack_qkv_kernel<<<(512 * 1536 + 255) / 256, 256>>>(Wq, Wk, Wv, bq, bk, bv,
                                                       PWqkv.h, PWqkv.l, bqkv);

    int c0, c1;
    // ---- pair 1: Z = Ar@srcr + srcr  ||  T1 = srco@Wo1 ----
    {
        GDesc dZ = mkDesc(PAr, 2048, (long)2048*2048, PSr, 304, (long)2048*304,
                          nullptr, srcr, (long)2048*300, nullptr, 0,
                          PZ, 304, (long)2048*304, 2048, 300, 2048, B_, 0, 0, &c0);
        GDesc dT1 = mkDesc(PSo, 1024, 0, PWo1, 1024, 0, nullptr, nullptr, 0,
                           T1, 0, PT1, 1024, 0, ROWS_O, 1024, 1024, 1, 0, 0, &c1);
        launchPair(dZ, c0, dT1, c1);
    }
    // ---- pair 2: H1r = relu(Z@Wr1)  ||  H1o = relu(Ao@T1 + T1) ----
    {
        GDesc dH1r = mkDesc(PZ, 304, 0, PWr1, 1024, 0, nullptr, nullptr, 0,
                            nullptr, 0, PH1r, 1024, 0, TOK, 1024, 300, 1, 1, 0, &c0);
        GDesc dH1o = mkDesc(PAo, 512, (long)512*512, PT1, 1024, (long)512*1024,
                            nullptr, T1, (long)512*1024, nullptr, 0,
                            PH1o, 1024, (long)512*1024, 512, 1024, 512, B_, 1, 0, &c1);
        launchPair(dH1r, c0, dH1o, c1);
    }
    // ---- pair 3: T4 = H1r@Wr2  ||  T2 = H1o@Wo2 ----
    {
        GDesc dT4 = mkDesc(PH1r, 1024, 0, PWr2, 512, 0, nullptr, nullptr, 0,
                           T4, 0, PT4, 512, 0, TOK, 512, 1024, 1, 0, 0, &c0);
        GDesc dT2 = mkDesc(PH1o, 1024, 0, PWo2, 512, 0, nullptr, nullptr, 0,
                           T2, 0, PT2, 512, 0, ROWS_O, 512, 1024, 1, 0, 0, &c1);
        launchPair(dT4, c0, dT2, c1);
    }
    // ---- pair 4: Gr = relu(Ar@T4 + T4)  ||  Go -> cat right half ----
    {
        GDesc dGr = mkDesc(PAr, 2048, (long)2048*2048, PT4, 512, (long)2048*512,
                           nullptr, T4, (long)2048*512, nullptr, 0,
                           PGr, 512, (long)2048*512, 2048, 512, 2048, B_, 1, 0, &c0);
        GDesc dGo = mkDesc(PAo, 512, (long)512*512, PT2, 512, (long)512*512,
                           nullptr, T2, (long)512*512, nullptr, 0,
                           PCatR, 1024, (long)512*1024, 512, 512, 512, B_, 1, 0, &c1);
        launchPair(dGr, c0, dGo, c1);
    }
    // ---- QKV (N=1536) ----
    {
        GDesc dQKV = mkDesc(PGr, 512, 0, PWqkv, 1536, 0, bqkv, nullptr, 0,
                            QKV, 0, NONE, 0, 0, TOK, 1536, 512, 1, 0, 0, &c0);
        launchOne(dQKV, c0);
    }
    // ---- attention ----
    {
        dim3 grid(SEGS, H_, 2);
        attn_mean_kernel<<<grid, 128>>>(QKV, POm.h, POm.l);
    }
    // ---- Wp projection -> cat left half (row-permuted) ----
    {
        GDesc dWp = mkDesc(POm, 512, 0, PWp, 512, 0, bp, nullptr, 0,
                           nullptr, 0, PCat, 1024, 0, 4096, 512, 512, 1, 0, 1, &c0);
        launchOne(dWp, c0);
    }
    // ---- final projection ----
    {
        GDesc dF = mkDesc(PCat, 1024, 0, PWe, 512, 0, be, nullptr, 0,
                          out, 0, NONE, 0, 0, OUT_ROWS, 512, 1024, 1, 0, 0, &c0);
        launchOne(dF, c0);
    }
}

// round 15
// speedup vs baseline: 1.3330x; 1.3330x over previous
#include <cuda_runtime.h>
#include <cuda_bf16.h>
#include <cstdint>

// ---------------------------------------------------------------------------
// Problem constants: B=8, NT=32, NO=8, C=512, VD=1024, RD=300, H=4
// ---------------------------------------------------------------------------
#define B_  8
#define C_  512
#define H_  4
#define DH_ 128
#define SEGS 2048
#define TOK  16384
#define ROWS_O 4096
#define OUT_ROWS 4096

// ---------------------------------------------------------------------------
// fp32 scratch
// ---------------------------------------------------------------------------
__device__ float g_QKV[TOK * 1536];
__device__ float g_bqkv[1536];

// bf16 hi/lo plane scratch
__device__ __nv_bfloat16 pAo_h [8*512*512],    pAo_l [8*512*512];
__device__ __nv_bfloat16 pAr_h [8*2048*2048],  pAr_l [8*2048*2048];
__device__ __nv_bfloat16 pSo_h [4096*1024],    pSo_l [4096*1024];
__device__ __nv_bfloat16 pSr_h [16384*304],    pSr_l [16384*304];   // ld=304
__device__ __nv_bfloat16 pWo1_h[1024*1024],    pWo1_l[1024*1024];
__device__ __nv_bfloat16 pWo2_h[1024*512],     pWo2_l[1024*512];
__device__ __nv_bfloat16 pWr1_h[300*1024],     pWr1_l[300*1024];
__device__ __nv_bfloat16 pWr2_h[1024*512],     pWr2_l[1024*512];
__device__ __nv_bfloat16 pWqkv_h[512*1536],    pWqkv_l[512*1536];
__device__ __nv_bfloat16 pWp_h [512*512],      pWp_l [512*512];
__device__ __nv_bfloat16 pWe_h [1024*512],     pWe_l [1024*512];
__device__ __nv_bfloat16 pT1_h [4096*1024],    pT1_l [4096*1024];
__device__ __nv_bfloat16 pH1o_h[4096*1024],    pH1o_l[4096*1024];
__device__ __nv_bfloat16 pT2_h [4096*512],     pT2_l [4096*512];
__device__ __nv_bfloat16 pZ_h  [16384*304],    pZ_l  [16384*304];   // ld=304
__device__ __nv_bfloat16 pH1r_h[16384*1024],   pH1r_l[16384*1024];
__device__ __nv_bfloat16 pT4_h [16384*512],    pT4_l [16384*512];
__device__ __nv_bfloat16 pGr_h [16384*512],    pGr_l [16384*512];
__device__ __nv_bfloat16 pOm_h [4096*512],     pOm_l [4096*512];
__device__ __nv_bfloat16 pCat_h[4096*1024],    pCat_l[4096*1024];

// ---------------------------------------------------------------------------
// helpers
// ---------------------------------------------------------------------------
__device__ __forceinline__ uint32_t smem_u32(const void* p) {
    uint32_t a;
    asm("{ .reg .u64 t; cvta.to.shared.u64 t, %1; cvt.u32.u64 %0, t; }"
        : "=r"(a) : "l"(p));
    return a;
}
__device__ __forceinline__ void cp16(uint32_t dst, const void* src, int sz) {
    asm volatile("cp.async.cg.shared.global [%0], [%1], 16, %2;"
                 :: "r"(dst), "l"(src), "r"(sz));
}
__device__ __forceinline__ void cp_commit() {
    asm volatile("cp.async.commit_group;");
}
__device__ __forceinline__ void cp_wait(int pend) {
    if (pend >= 1) asm volatile("cp.async.wait_group 1;");
    else           asm volatile("cp.async.wait_group 0;");
}
__device__ __forceinline__ void ldsm4(uint32_t* r, uint32_t addr) {
    asm volatile("ldmatrix.sync.aligned.m8n8.x4.shared.b16 {%0,%1,%2,%3}, [%4];"
                 : "=r"(r[0]), "=r"(r[1]), "=r"(r[2]), "=r"(r[3]) : "r"(addr));
}
__device__ __forceinline__ void ldsm4t(uint32_t* r, uint32_t addr) {
    asm volatile("ldmatrix.sync.aligned.m8n8.x4.trans.shared.b16 {%0,%1,%2,%3}, [%4];"
                 : "=r"(r[0]), "=r"(r[1]), "=r"(r[2]), "=r"(r[3]) : "r"(addr));
}
__device__ __forceinline__ void mma16816(float* d, const uint32_t* a, const uint32_t* b) {
    asm volatile(
        "mma.sync.aligned.m16n8k16.row.col.f32.bf16.bf16.f32 "
        "{%0,%1,%2,%3}, {%4,%5,%6,%7}, {%8,%9}, {%0,%1,%2,%3};"
        : "+f"(d[0]), "+f"(d[1]), "+f"(d[2]), "+f"(d[3])
        : "r"(a[0]), "r"(a[1]), "r"(a[2]), "r"(a[3]), "r"(b[0]), "r"(b[1]));
}
__device__ __forceinline__ void split1(float x, __nv_bfloat16& h, __nv_bfloat16& l) {
    h = __float2bfloat16(x);
    l = __float2bfloat16(x - __bfloat162float(h));
}

// ---------------------------------------------------------------------------
// SMEM stage layout (bytes)
// ---------------------------------------------------------------------------
#define PITCH_A 80
#define PITCH_B 272
#define OFF_AL 10240
#define OFF_BH 20480
#define OFF_BL 29184
#define STAGE_B 37888
#define NSTAGE 3
#define SMEM_DYN (NSTAGE * STAGE_B)     // 113664 -> 2 CTAs/SM

// ---------------------------------------------------------------------------
// GEMM descriptor (passed by value; two per launch -> merged grids)
// ---------------------------------------------------------------------------
struct GDesc {
    const __nv_bfloat16 *Ah, *Al, *Bh, *Bl;
    const float *bias, *X;
    const __nv_bfloat16 *Xh, *Xl;        // plane-form X (alternative to fp32 X)
    float* Cf;
    __nv_bfloat16 *Ch, *Cl;
    long sAp, sBp, sX, sXp, sCf, sCo;
    int lda, ldb, ldx, ldo;
    int M, N, K, relu, rowmap;
    int gx, gy;
};

// ---------------------------------------------------------------------------
// HMMA bf16-split GEMM v7: 128 threads (2x2 warps, 64x64 warp tile),
// 128x128 CTA tile, 3-stage cp.async pipeline, 2 CTAs/SM.
// B fragments for BOTH k-substeps preloaded; A fragments per-mt.
// ---------------------------------------------------------------------------
__global__ __launch_bounds__(128, 2)
void mm2_kernel(GDesc d0, GDesc d1, int boundary)
{
    extern __shared__ char smem[];
    const uint32_t sbase = smem_u32(smem);

    const bool second = ((int)blockIdx.x >= boundary);
    const GDesc& d = second ? d1 : d0;
    const int local = (int)blockIdx.x - (second ? boundary : 0);
    const int gxy = d.gx * d.gy;
    const int bz  = local / gxy;
    const int rem = local - bz * gxy;
    const int by  = rem / d.gx;
    const int bxx = rem - by * d.gx;

    const __nv_bfloat16* Ah = d.Ah + (long)bz * d.sAp;
    const __nv_bfloat16* Al = d.Al + (long)bz * d.sAp;
    const __nv_bfloat16* Bh = d.Bh + (long)bz * d.sBp;
    const __nv_bfloat16* Bl = d.Bl + (long)bz * d.sBp;
    float* Cf = d.Cf ? (d.Cf + (long)bz * d.sCf) : nullptr;
    __nv_bfloat16* Ch = d.Ch ? (d.Ch + (long)bz * d.sCo) : nullptr;
    __nv_bfloat16* Cl = d.Cl ? (d.Cl + (long)bz * d.sCo) : nullptr;
    const float* X = d.X ? (d.X + (long)bz * d.sX) : nullptr;
    const __nv_bfloat16* Xh = d.Xh ? (d.Xh + (long)bz * d.sXp) : nullptr;
    const __nv_bfloat16* Xl = d.Xl ? (d.Xl + (long)bz * d.sXp) : nullptr;
    const int lda = d.lda, ldb = d.ldb, N = d.N, K = d.K;

    const int tid  = threadIdx.x;        // 0..127
    const int wid  = tid >> 5;           // 0..3
    const int lane = tid & 31;
    const int row0 = by * 128;
    const int col0 = bxx * 128;
    const int wm = wid >> 1;             // 0..1 -> rows wm*64
    const int wn = wid & 1;              // 0..1 -> cols wn*64

    float acc[4][8][4];
    #pragma unroll
    for (int mt = 0; mt < 4; ++mt)
        #pragma unroll
        for (int nt = 0; nt < 8; ++nt)
            #pragma unroll
            for (int e = 0; e < 4; ++e) acc[mt][nt][e] = 0.f;

    const int nch = (K + 31) >> 5;

    auto issueStage = [&](int c, int buf) {
        const int k0 = c << 5;
        const uint32_t sb = sbase + buf * STAGE_B;
        #pragma unroll
        for (int i = 0; i < 4; ++i) {
            const int ch  = tid + i * 128;
            const int row = ch >> 2;
            const int o8  = (ch & 3) * 8;
            const int rem2 = K - (k0 + o8);
            const int sz  = rem2 >= 8 ? 16 : (rem2 > 0 ? rem2 * 2 : 0);
            const long so = (long)(row0 + row) * lda + (sz ? (k0 + o8) : 0);
            const uint32_t dst = sb + row * PITCH_A + (ch & 3) * 16;
            cp16(dst,          Ah + so, sz);
            cp16(dst + OFF_AL, Al + so, sz);
        }
        #pragma unroll
        for (int i = 0; i < 4; ++i) {
            const int ch   = tid + i * 128;
            const int krow = ch >> 4;
            const int no8  = (ch & 15) * 8;
            const int remn = N - (col0 + no8);
            int sz = (k0 + krow < K) ? (remn >= 8 ? 16 : (remn > 0 ? remn * 2 : 0)) : 0;
            const long so = sz ? ((long)(k0 + krow) * ldb + col0 + no8) : 0;
            const uint32_t dst = sb + OFF_BH + krow * PITCH_B + (ch & 15) * 16;
            cp16(dst,                     Bh + so, sz);
            cp16(dst + (OFF_BL - OFF_BH), Bl + so, sz);
        }
    };

    auto computeChunk = [&](int buf) {
        const uint32_t sb = sbase + buf * STAGE_B;
        // B fragments for BOTH substeps, preloaded
        uint32_t bhf[2][8][2], blf[2][8][2];
        #pragma unroll
        for (int s2 = 0; s2 < 2; ++s2) {
            const int kb = s2 * 16;
            #pragma unroll
            for (int pair = 0; pair < 4; ++pair) {
                const uint32_t krow = kb + ((lane >> 3) & 1) * 8 + (lane & 7);
                const uint32_t ncol = wn * 64 + pair * 16 + (lane >> 4) * 8;
                const uint32_t boff = sb + OFF_BH + krow * PITCH_B + ncol * 2;
                uint32_t r4[4];
                ldsm4t(r4, boff);
                bhf[s2][pair * 2][0] = r4[0]; bhf[s2][pair * 2][1] = r4[1];
                bhf[s2][pair * 2 + 1][0] = r4[2]; bhf[s2][pair * 2 + 1][1] = r4[3];
                ldsm4t(r4, boff + (OFF_BL - OFF_BH));
                blf[s2][pair * 2][0] = r4[0]; blf[s2][pair * 2][1] = r4[1];
                blf[s2][pair * 2 + 1][0] = r4[2]; blf[s2][pair * 2 + 1][1] = r4[3];
            }
        }
        // A per-mt, 24 MMAs each
        #pragma unroll
        for (int s2 = 0; s2 < 2; ++s2) {
            const int kb = s2 * 16;
            #pragma unroll
            for (int mt = 0; mt < 4; ++mt) {
                uint32_t ahf[4], alf[4];
                const uint32_t arow = wm * 64 + mt * 16 + (lane & 15);
                const uint32_t aoff = sb + arow * PITCH_A + (kb + ((lane >> 4) * 8)) * 2;
                ldsm4(ahf, aoff);
                ldsm4(alf, aoff + OFF_AL);
                #pragma unroll
                for (int nt = 0; nt < 8; ++nt)
                    mma16816(acc[mt][nt], ahf, bhf[s2][nt]);
                #pragma unroll
                for (int nt = 0; nt < 8; ++nt)
                    mma16816(acc[mt][nt], alf, bhf[s2][nt]);
                #pragma unroll
                for (int nt = 0; nt < 8; ++nt)
                    mma16816(acc[mt][nt], ahf, blf[s2][nt]);
            }
        }
    };

    issueStage(0, 0); cp_commit();
    if (nch > 1) { issueStage(1, 1); cp_commit(); }

    for (int c = 0; c < nch; ++c) {
        cp_wait((c + 2 <= nch) ? ((c + 1 < nch) ? 1 : 0) : 0);
        __syncthreads();
        if (c + 2 < nch) { issueStage(c + 2, (c + 2) % NSTAGE); cp_commit(); }
        computeChunk(c % NSTAGE);
    }

    // epilogue
    #pragma unroll
    for (int mt = 0; mt < 4; ++mt) {
        #pragma unroll
        for (int nt = 0; nt < 8; ++nt) {
            const int col = col0 + wn * 64 + nt * 8 + (lane & 3) * 2;
            if (col >= N) continue;
            #pragma unroll
            for (int half = 0; half < 2; ++half) {
                const int row = row0 + wm * 64 + mt * 16 + (lane >> 2) + half * 8;
                float2 v = make_float2(acc[mt][nt][half * 2], acc[mt][nt][half * 2 + 1]);
                if (d.bias) {
                    const float2 bv = *(const float2*)(d.bias + col);
                    v.x += bv.x; v.y += bv.y;
                }
                if (X) {
                    const float2 xv = *(const float2*)(X + (long)row * N + col);
                    v.x += xv.x; v.y += xv.y;
                } else if (Xh) {
                    const long ox = (long)row * d.ldx + col;
                    const __nv_bfloat162 xh2 = *(const __nv_bfloat162*)(Xh + ox);
                    const __nv_bfloat162 xl2 = *(const __nv_bfloat162*)(Xl + ox);
                    v.x += __bfloat162float(xh2.x) + __bfloat162float(xl2.x);
                    v.y += __bfloat162float(xh2.y) + __bfloat162float(xl2.y);
                }
                if (d.relu) { v.x = fmaxf(v.x, 0.f); v.y = fmaxf(v.y, 0.f); }
                int orow = row;
                if (d.rowmap) {
                    if (row < 2048) orow = ((row >> 3) << 4) + (row & 7);
                    else { const int a = row - 2048; orow = ((a >> 3) << 4) + 8 + (a & 7); }
                }
                if (Cf) *(float2*)(Cf + (long)orow * N + col) = v;
                if (Ch) {
                    __nv_bfloat16 hx, lx, hy, ly;
                    split1(v.x, hx, lx); split1(v.y, hy, ly);
                    const long o = (long)orow * d.ldo + col;
                    *(uint32_t*)(Ch + o) =
                        (uint32_t)__bfloat16_as_ushort(hx) | ((uint32_t)__bfloat16_as_ushort(hy) << 16);
                    *(uint32_t*)(Cl + o) =
                        (uint32_t)__bfloat16_as_ushort(lx) | ((uint32_t)__bfloat16_as_ushort(ly) << 16);
                }
            }
        }
    }
}

// ---------------------------------------------------------------------------
// Multi-job fp32 -> bf16 hi/lo plane convert (one launch)
// ---------------------------------------------------------------------------
#define NCVT 10
struct CvtJobs {
    const float* in[NCVT];
    __nv_bfloat16* h[NCVT];
    __nv_bfloat16* l[NCVT];
    long n[NCVT];
    int cols[NCVT], ldo[NCVT];
    int start[NCVT + 1];
};

__global__ __launch_bounds__(256)
void cvt_multi_kernel(CvtJobs J)
{
    const int bx = blockIdx.x;
    int j = 0;
    #pragma unroll
    for (int t = 0; t < NCVT - 1; ++t) if (bx >= J.start[t + 1]) j = t + 1;
    const long i = ((long)(bx - J.start[j]) * 256 + threadIdx.x) * 4;
    if (i >= J.n[j]) return;
    const float4 v = *(const float4*)(J.in[j] + i);
    long o;
    const int cols = J.cols[j], ldo = J.ldo[j];
    if (cols == ldo) o = i;
    else { const long r = i / cols; o = r * ldo + (int)(i - r * cols); }
    __nv_bfloat16 hh[4], ll[4];
    split1(v.x, hh[0], ll[0]); split1(v.y, hh[1], ll[1]);
    split1(v.z, hh[2], ll[2]); split1(v.w, hh[3], ll[3]);
    *(uint2*)(J.h[j] + o) = *(uint2*)hh;
    *(uint2*)(J.l[j] + o) = *(uint2*)ll;
}

__global__ __launch_bounds__(256)
void pack_qkv_kernel(const float* __restrict__ Wq, const float* __restrict__ Wk,
                     const float* __restrict__ Wv, const float* __restrict__ bq,
                     const float* __restrict__ bk, const float* __restrict__ bv,
                     __nv_bfloat16* __restrict__ h, __nv_bfloat16* __restrict__ l,
                     float* __restrict__ bias)
{
    const int idx = blockIdx.x * 256 + threadIdx.x;
    if (idx < 512 * 1536) {
        const int k = idx / 1536, n = idx % 1536, sel = n >> 9;
        const float* W = (sel == 0) ? Wq : (sel == 1) ? Wk : Wv;
        const float v = W[k * 512 + (n & 511)];
        __nv_bfloat16 hh, ll; split1(v, hh, ll);
        h[idx] = hh; l[idx] = ll;
    }
    if (idx < 1536) {
        const int sel = idx >> 9;
        const float* bb = (sel == 0) ? bq : (sel == 1) ? bk : bv;
        bias[idx] = bb[idx & 511];
    }
}

// ---------------------------------------------------------------------------
// Segmented MHA, both paths in one launch (blockIdx.z = path)
// ---------------------------------------------------------------------------
__global__ __launch_bounds__(128)
void attn_mean_kernel(const float* __restrict__ QKV,
                      __nv_bfloat16* __restrict__ OmH, __nv_bfloat16* __restrict__ OmL)
{
    const int s = blockIdx.x, h = blockIdx.y, path = blockIdx.z, tid = threadIdx.x;
    __shared__ float qs[8][DH_ + 1], ks[8][DH_ + 1], vs[8][DH_ + 1];
    __shared__ float sc[8][9], wj[8];

    #pragma unroll
    for (int i = 0; i < 8; ++i) {
        int g;
        if (path == 0) g = s * 8 + i;
        else { const int t = s >> 3, j = s & 7; g = t * 64 + i * 8 + j; }
        const long off = (long)g * 1536 + h * DH_ + tid;
        qs[i][tid] = QKV[off];
        ks[i][tid] = QKV[off + 512];
        vs[i][tid] = QKV[off + 1024];
    }
    __syncthreads();

    if (tid < 64) {
        const int i = tid >> 3, j = tid & 7;
        float d = 0.f;
        #pragma unroll 16
        for (int k = 0; k < DH_; ++k) d = fmaf(qs[i][k], ks[j][k], d);
        sc[i][j] = d * 0.08838834764831845f;
    }
    __syncthreads();
    if (tid < 8) {
        const int i = tid;
        float m = -1e30f;
        #pragma unroll
        for (int j = 0; j < 8; ++j) m = fmaxf(m, sc[i][j]);
        float e[8], sum = 0.f;
        #pragma unroll
        for (int j = 0; j < 8; ++j) { e[j] = __expf(sc[i][j] - m); sum += e[j]; }
        const float inv = 1.f / sum;
        #pragma unroll
        for (int j = 0; j < 8; ++j) sc[i][j] = e[j] * inv;
    }
    __syncthreads();
    if (tid < 8) {
        const int j = tid;
        float w = 0.f;
        #pragma unroll
        for (int i = 0; i < 8; ++i) w += sc[i][j];
        wj[j] = w * 0.125f;
    }
    __syncthreads();
    float o = 0.f;
    #pragma unroll
    for (int j = 0; j < 8; ++j) o = fmaf(wj[j], vs[j][tid], o);

    const long off = (long)(path * SEGS + s) * 512 + h * DH_ + tid;
    __nv_bfloat16 hh, ll; split1(o, hh, ll);
    OmH[off] = hh; OmL[off] = ll;
}

// ---------------------------------------------------------------------------
// Host
// ---------------------------------------------------------------------------
#define SYM(p, s) cudaGetSymbolAddress((void**)&p, s)

struct Planes { __nv_bfloat16 *h, *l; };

static GDesc mkDesc(Planes A, int lda, long sAp, Planes Bp, int ldb, long sBp,
                    const float* bias, const float* X, long sX,
                    Planes Xp, int ldx, long sXp,
                    float* Cf, long sCf, Planes Co, int ldo, long sCo,
                    int M, int N, int K, int nb, int relu, int rowmap,
                    int* ctas)
{
    GDesc d;
    d.Ah = A.h; d.Al = A.l; d.Bh = Bp.h; d.Bl = Bp.l;
    d.bias = bias; d.X = X; d.Xh = Xp.h; d.Xl = Xp.l;
    d.Cf = Cf; d.Ch = Co.h; d.Cl = Co.l;
    d.sAp = sAp; d.sBp = sBp; d.sX = sX; d.sXp = sXp; d.sCf = sCf; d.sCo = sCo;
    d.lda = lda; d.ldb = ldb; d.ldx = ldx; d.ldo = ldo;
    d.M = M; d.N = N; d.K = K; d.relu = relu; d.rowmap = rowmap;
    d.gx = (N + 127) / 128; d.gy = M / 128;
    *ctas = d.gx * d.gy * nb;
    return d;
}

static inline void launchPair(const GDesc& a, int ca, const GDesc& b, int cb)
{
    mm2_kernel<<<ca + cb, 128, SMEM_DYN>>>(a, b, ca);
}
static inline void launchOne(const GDesc& a, int ca)
{
    mm2_kernel<<<ca, 128, SMEM_DYN>>>(a, a, ca);
}

extern "C" void kernel_launch(void* const* d_in, const int* in_sizes, int n_in,
                              void* d_out, int out_size)
{
    const float* Ao   = (const float*)d_in[0];
    const float* srco = (const float*)d_in[1];
    const float* Ar   = (const float*)d_in[2];
    const float* srcr = (const float*)d_in[3];
    const float* Wo1  = (const float*)d_in[4];
    const float* Wo2  = (const float*)d_in[5];
    const float* Wr1  = (const float*)d_in[6];
    const float* Wr2  = (const float*)d_in[7];
    const float* Wq   = (const float*)d_in[8];
    const float* bq   = (const float*)d_in[9];
    const float* Wk   = (const float*)d_in[10];
    const float* bk   = (const float*)d_in[11];
    const float* Wv   = (const float*)d_in[12];
    const float* bv   = (const float*)d_in[13];
    const float* Wp   = (const float*)d_in[14];
    const float* bp   = (const float*)d_in[15];
    const float* We   = (const float*)d_in[16];
    const float* be   = (const float*)d_in[17];
    float* out = (float*)d_out;

    cudaFuncSetAttribute(mm2_kernel, cudaFuncAttributeMaxDynamicSharedMemorySize, SMEM_DYN);

    float *QKV, *bqkv;
    SYM(QKV, g_QKV); SYM(bqkv, g_bqkv);

    Planes PAo, PAr, PSo, PSr, PWo1, PWo2, PWr1, PWr2, PWqkv, PWp, PWe;
    Planes PT1, PH1o, PT2, PZ, PH1r, PT4, PGr, POm, PCat;
    SYM(PAo.h, pAo_h);   SYM(PAo.l, pAo_l);
    SYM(PAr.h, pAr_h);   SYM(PAr.l, pAr_l);
    SYM(PSo.h, pSo_h);   SYM(PSo.l, pSo_l);
    SYM(PSr.h, pSr_h);   SYM(PSr.l, pSr_l);
    SYM(PWo1.h, pWo1_h); SYM(PWo1.l, pWo1_l);
    SYM(PWo2.h, pWo2_h); SYM(PWo2.l, pWo2_l);
    SYM(PWr1.h, pWr1_h); SYM(PWr1.l, pWr1_l);
    SYM(PWr2.h, pWr2_h); SYM(PWr2.l, pWr2_l);
    SYM(PWqkv.h, pWqkv_h); SYM(PWqkv.l, pWqkv_l);
    SYM(PWp.h, pWp_h);   SYM(PWp.l, pWp_l);
    SYM(PWe.h, pWe_h);   SYM(PWe.l, pWe_l);
    SYM(PT1.h, pT1_h);   SYM(PT1.l, pT1_l);
    SYM(PH1o.h, pH1o_h); SYM(PH1o.l, pH1o_l);
    SYM(PT2.h, pT2_h);   SYM(PT2.l, pT2_l);
    SYM(PZ.h, pZ_h);     SYM(PZ.l, pZ_l);
    SYM(PH1r.h, pH1r_h); SYM(PH1r.l, pH1r_l);
    SYM(PT4.h, pT4_h);   SYM(PT4.l, pT4_l);
    SYM(PGr.h, pGr_h);   SYM(PGr.l, pGr_l);
    SYM(POm.h, pOm_h);   SYM(POm.l, pOm_l);
    SYM(PCat.h, pCat_h); SYM(PCat.l, pCat_l);

    const Planes NONE = {nullptr, nullptr};
    Planes PCatR = {PCat.h + 512, PCat.l + 512};   // right half of cat

    // ---- one merged conversion launch ----
    {
        CvtJobs J;
        const float* ins[NCVT] = {Ar, srcr, srco, Ao, Wo1, Wo2, Wr1, Wr2, Wp, We};
        Planes      ps [NCVT] = {PAr, PSr, PSo, PAo, PWo1, PWo2, PWr1, PWr2, PWp, PWe};
        long        ns [NCVT] = {(long)8*2048*2048, (long)16384*300, (long)4096*1024,
                                 (long)8*512*512, (long)1024*1024, (long)1024*512,
                                 (long)300*1024, (long)1024*512, (long)512*512,
                                 (long)1024*512};
        int         cs [NCVT] = {2048, 300, 1024, 512, 1024, 512, 1024, 512, 512, 512};
        int         ld [NCVT] = {2048, 304, 1024, 512, 1024, 512, 1024, 512, 512, 512};
        int cum = 0;
        for (int j = 0; j < NCVT; ++j) {
            J.in[j] = ins[j]; J.h[j] = ps[j].h; J.l[j] = ps[j].l;
            J.n[j] = ns[j]; J.cols[j] = cs[j]; J.ldo[j] = ld[j];
            J.start[j] = cum;
            cum += (int)((ns[j] + 1023) / 1024);
        }
        J.start[NCVT] = cum;
        cvt_multi_kernel<<<cum, 256>>>(J);
    }
    pack_qkv_kernel<<<(512 * 1536 + 255) / 256, 256>>>(Wq, Wk, Wv, bq, bk, bv,
                                                       PWqkv.h, PWqkv.l, bqkv);

    int c0, c1;
    // ---- pair 1: Z = Ar@srcr + srcr  ||  T1 = srco@Wo1 (planes only) ----
    {
        GDesc dZ = mkDesc(PAr, 2048, (long)2048*2048, PSr, 304, (long)2048*304,
                          nullptr, srcr, (long)2048*300, NONE, 0, 0,
                          nullptr, 0, PZ, 304, (long)2048*304,
                          2048, 300, 2048, B_, 0, 0, &c0);
        GDesc dT1 = mkDesc(PSo, 1024, 0, PWo1, 1024, 0, nullptr, nullptr, 0,
                           NONE, 0, 0, nullptr, 0, PT1, 1024, 0,
                           ROWS_O, 1024, 1024, 1, 0, 0, &c1);
        launchPair(dZ, c0, dT1, c1);
    }
    // ---- pair 2: H1r = relu(Z@Wr1)  ||  H1o = relu(Ao@T1 + T1planes) ----
    {
        GDesc dH1r = mkDesc(PZ, 304, 0, PWr1, 1024, 0, nullptr, nullptr, 0,
                            NONE, 0, 0, nullptr, 0, PH1r, 1024, 0,
                            TOK, 1024, 300, 1, 1, 0, &c0);
        GDesc dH1o = mkDesc(PAo, 512, (long)512*512, PT1, 1024, (long)512*1024,
                            nullptr, nullptr, 0, PT1, 1024, (long)512*1024,
                            nullptr, 0, PH1o, 1024, (long)512*1024,
                            512, 1024, 512, B_, 1, 0, &c1);
        launchPair(dH1r, c0, dH1o, c1);
    }
    // ---- pair 3: T4 = H1r@Wr2 (planes)  ||  T2 = H1o@Wo2 (planes) ----
    {
        GDesc dT4 = mkDesc(PH1r, 1024, 0, PWr2, 512, 0, nullptr, nullptr, 0,
                           NONE, 0, 0, nullptr, 0, PT4, 512, 0,
                           TOK, 512, 1024, 1, 0, 0, &c0);
        GDesc dT2 = mkDesc(PH1o, 1024, 0, PWo2, 512, 0, nullptr, nullptr, 0,
                           NONE, 0, 0, nullptr, 0, PT2, 512, 0,
                           ROWS_O, 512, 1024, 1, 0, 0, &c1);
        launchPair(dT4, c0, dT2, c1);
    }
    // ---- pair 4: Gr = relu(Ar@T4 + T4planes)  ||  Go -> cat right half ----
    {
        GDesc dGr = mkDesc(PAr, 2048, (long)2048*2048, PT4, 512, (long)2048*512,
                           nullptr, nullptr, 0, PT4, 512, (long)2048*512,
                           nullptr, 0, PGr, 512, (long)2048*512,
                           2048, 512, 2048, B_, 1, 0, &c0);
        GDesc dGo = mkDesc(PAo, 512, (long)512*512, PT2, 512, (long)512*512,
                           nullptr, nullptr, 0, PT2, 512, (long)512*512,
                           nullptr, 0, PCatR, 1024, (long)512*1024,
                           512, 512, 512, B_, 1, 0, &c1);
        launchPair(dGr, c0, dGo, c1);
    }
    // ---- QKV (N=1536) ----
    {
        GDesc dQKV = mkDesc(PGr, 512, 0, PWqkv, 1536, 0, bqkv, nullptr, 0,
                            NONE, 0, 0, QKV, 0, NONE, 0, 0,
                            TOK, 1536, 512, 1, 0, 0, &c0);
        launchOne(dQKV, c0);
    }
    // ---- attention ----
    {
        dim3 grid(SEGS, H_, 2);
        attn_mean_kernel<<<grid, 128>>>(QKV, POm.h, POm.l);
    }
    // ---- Wp projection -> cat left half (row-permuted) ----
    {
        GDesc dWp = mkDesc(POm, 512, 0, PWp, 512, 0, bp, nullptr, 0,
                           NONE, 0, 0, nullptr, 0, PCat, 1024, 0,
                           4096, 512, 512, 1, 0, 1, &c0);
        launchOne(dWp, c0);
    }
    // ---- final projection ----
    {
        GDesc dF = mkDesc(PCat, 1024, 0, PWe, 512, 0, be, nullptr, 0,
                          NONE, 0, 0, out, 0, NONE, 0, 0,
                          OUT_ROWS, 512, 1024, 1, 0, 0, &c0);
        launchOne(dF, c0);
    }
}

// round 16
// speedup vs baseline: 1.4556x; 1.0919x over previous
#include <cuda_runtime.h>
#include <cuda_bf16.h>
#include <cstdint>

// ---------------------------------------------------------------------------
// Problem constants: B=8, NT=32, NO=8, C=512, VD=1024, RD=300, H=4
// ---------------------------------------------------------------------------
#define B_  8
#define C_  512
#define H_  4
#define DH_ 128
#define SEGS 2048
#define TOK  16384
#define ROWS_O 4096
#define OUT_ROWS 4096

// ---------------------------------------------------------------------------
// fp32 scratch
// ---------------------------------------------------------------------------
__device__ float g_T1 [ROWS_O * 1024];
__device__ float g_T2 [ROWS_O * 512];
__device__ float g_T4 [TOK * 512];
__device__ float g_QKV[TOK * 1536];
__device__ float g_bqkv[1536];
__device__ float g_E  [4096 * 512];     // (Om@Wf + b2), row-permuted
__device__ float g_b2 [512];            // bp@We_top + be

// bf16 hi/lo plane scratch
__device__ __nv_bfloat16 pAo_h [8*512*512],    pAo_l [8*512*512];
__device__ __nv_bfloat16 pAr_h [8*2048*2048],  pAr_l [8*2048*2048];
__device__ __nv_bfloat16 pSo_h [4096*1024],    pSo_l [4096*1024];
__device__ __nv_bfloat16 pSr_h [16384*304],    pSr_l [16384*304];   // ld=304
__device__ __nv_bfloat16 pWo1_h[1024*1024],    pWo1_l[1024*1024];
__device__ __nv_bfloat16 pWo2_h[1024*512],     pWo2_l[1024*512];
__device__ __nv_bfloat16 pWr1_h[300*1024],     pWr1_l[300*1024];
__device__ __nv_bfloat16 pWr2_h[1024*512],     pWr2_l[1024*512];
__device__ __nv_bfloat16 pWqkv_h[512*1536],    pWqkv_l[512*1536];
__device__ __nv_bfloat16 pWp_h [512*512],      pWp_l [512*512];
__device__ __nv_bfloat16 pWe_h [1024*512],     pWe_l [1024*512];
__device__ __nv_bfloat16 pWf_h [512*512],      pWf_l [512*512];     // Wp@We_top
__device__ __nv_bfloat16 pT1_h [4096*1024],    pT1_l [4096*1024];
__device__ __nv_bfloat16 pH1o_h[4096*1024],    pH1o_l[4096*1024];
__device__ __nv_bfloat16 pT2_h [4096*512],     pT2_l [4096*512];
__device__ __nv_bfloat16 pZ_h  [16384*304],    pZ_l  [16384*304];   // ld=304
__device__ __nv_bfloat16 pH1r_h[16384*1024],   pH1r_l[16384*1024];
__device__ __nv_bfloat16 pT4_h [16384*512],    pT4_l [16384*512];
__device__ __nv_bfloat16 pGr_h [16384*512],    pGr_l [16384*512];
__device__ __nv_bfloat16 pGo_h [4096*512],     pGo_l [4096*512];
__device__ __nv_bfloat16 pOm_h [4096*512],     pOm_l [4096*512];

// ---------------------------------------------------------------------------
// helpers
// ---------------------------------------------------------------------------
__device__ __forceinline__ uint32_t smem_u32(const void* p) {
    uint32_t a;
    asm("{ .reg .u64 t; cvta.to.shared.u64 t, %1; cvt.u32.u64 %0, t; }"
        : "=r"(a) : "l"(p));
    return a;
}
__device__ __forceinline__ void cp16(uint32_t dst, const void* src, int sz) {
    asm volatile("cp.async.cg.shared.global [%0], [%1], 16, %2;"
                 :: "r"(dst), "l"(src), "r"(sz));
}
__device__ __forceinline__ void cp_commit() {
    asm volatile("cp.async.commit_group;");
}
__device__ __forceinline__ void cp_wait(int pend) {
    if (pend >= 1) asm volatile("cp.async.wait_group 1;");
    else           asm volatile("cp.async.wait_group 0;");
}
__device__ __forceinline__ void ldsm4(uint32_t* r, uint32_t addr) {
    asm volatile("ldmatrix.sync.aligned.m8n8.x4.shared.b16 {%0,%1,%2,%3}, [%4];"
                 : "=r"(r[0]), "=r"(r[1]), "=r"(r[2]), "=r"(r[3]) : "r"(addr));
}
__device__ __forceinline__ void ldsm4t(uint32_t* r, uint32_t addr) {
    asm volatile("ldmatrix.sync.aligned.m8n8.x4.trans.shared.b16 {%0,%1,%2,%3}, [%4];"
                 : "=r"(r[0]), "=r"(r[1]), "=r"(r[2]), "=r"(r[3]) : "r"(addr));
}
__device__ __forceinline__ void mma16816(float* d, const uint32_t* a, const uint32_t* b) {
    asm volatile(
        "mma.sync.aligned.m16n8k16.row.col.f32.bf16.bf16.f32 "
        "{%0,%1,%2,%3}, {%4,%5,%6,%7}, {%8,%9}, {%0,%1,%2,%3};"
        : "+f"(d[0]), "+f"(d[1]), "+f"(d[2]), "+f"(d[3])
        : "r"(a[0]), "r"(a[1]), "r"(a[2]), "r"(a[3]), "r"(b[0]), "r"(b[1]));
}
__device__ __forceinline__ void split1(float x, __nv_bfloat16& h, __nv_bfloat16& l) {
    h = __float2bfloat16(x);
    l = __float2bfloat16(x - __bfloat162float(h));
}

// ---------------------------------------------------------------------------
// SMEM stage layout (bytes)
// ---------------------------------------------------------------------------
#define PITCH_A 80
#define PITCH_B 272
#define OFF_AL 10240
#define OFF_BH 20480
#define OFF_BL 29184
#define STAGE_B 37888
#define NSTAGE 3
#define SMEM_DYN (NSTAGE * STAGE_B)     // 113664 -> 2 CTAs/SM

// ---------------------------------------------------------------------------
// GEMM descriptor (passed by value; two per launch -> merged grids)
// ---------------------------------------------------------------------------
struct GDesc {
    const __nv_bfloat16 *Ah, *Al, *Bh, *Bl;
    const float *bias, *X;
    float* Cf;
    __nv_bfloat16 *Ch, *Cl;
    long sAp, sBp, sX, sCf, sCo;
    int lda, ldb, ldo;
    int M, N, K, relu, rowmap;
    int gx, gy;
};

// ---------------------------------------------------------------------------
// HMMA bf16-split GEMM (R12 schedule, verbatim): 128 threads (2x2 warps,
// 64x64 warp tile), 128x128 CTA tile, 3-stage cp.async pipeline, 2 CTAs/SM.
// ---------------------------------------------------------------------------
__global__ __launch_bounds__(128, 2)
void mm2_kernel(GDesc d0, GDesc d1, int boundary)
{
    extern __shared__ char smem[];
    const uint32_t sbase = smem_u32(smem);

    const bool second = ((int)blockIdx.x >= boundary);
    const GDesc& d = second ? d1 : d0;
    const int local = (int)blockIdx.x - (second ? boundary : 0);
    const int gxy = d.gx * d.gy;
    const int bz  = local / gxy;
    const int rem = local - bz * gxy;
    const int by  = rem / d.gx;
    const int bxx = rem - by * d.gx;

    const __nv_bfloat16* Ah = d.Ah + (long)bz * d.sAp;
    const __nv_bfloat16* Al = d.Al + (long)bz * d.sAp;
    const __nv_bfloat16* Bh = d.Bh + (long)bz * d.sBp;
    const __nv_bfloat16* Bl = d.Bl + (long)bz * d.sBp;
    float* Cf = d.Cf ? (d.Cf + (long)bz * d.sCf) : nullptr;
    __nv_bfloat16* Ch = d.Ch ? (d.Ch + (long)bz * d.sCo) : nullptr;
    __nv_bfloat16* Cl = d.Cl ? (d.Cl + (long)bz * d.sCo) : nullptr;
    const float* X = d.X ? (d.X + (long)bz * d.sX) : nullptr;
    const int lda = d.lda, ldb = d.ldb, N = d.N, K = d.K;

    const int tid  = threadIdx.x;        // 0..127
    const int wid  = tid >> 5;           // 0..3
    const int lane = tid & 31;
    const int row0 = by * 128;
    const int col0 = bxx * 128;
    const int wm = wid >> 1;             // 0..1 -> rows wm*64
    const int wn = wid & 1;              // 0..1 -> cols wn*64

    float acc[4][8][4];
    #pragma unroll
    for (int mt = 0; mt < 4; ++mt)
        #pragma unroll
        for (int nt = 0; nt < 8; ++nt)
            #pragma unroll
            for (int e = 0; e < 4; ++e) acc[mt][nt][e] = 0.f;

    const int nch = (K + 31) >> 5;

    auto issueStage = [&](int c, int buf) {
        const int k0 = c << 5;
        const uint32_t sb = sbase + buf * STAGE_B;
        #pragma unroll
        for (int i = 0; i < 4; ++i) {
            const int ch  = tid + i * 128;
            const int row = ch >> 2;
            const int o8  = (ch & 3) * 8;
            const int rem2 = K - (k0 + o8);
            const int sz  = rem2 >= 8 ? 16 : (rem2 > 0 ? rem2 * 2 : 0);
            const long so = (long)(row0 + row) * lda + (sz ? (k0 + o8) : 0);
            const uint32_t dst = sb + row * PITCH_A + (ch & 3) * 16;
            cp16(dst,          Ah + so, sz);
            cp16(dst + OFF_AL, Al + so, sz);
        }
        #pragma unroll
        for (int i = 0; i < 4; ++i) {
            const int ch   = tid + i * 128;
            const int krow = ch >> 4;
            const int no8  = (ch & 15) * 8;
            const int remn = N - (col0 + no8);
            int sz = (k0 + krow < K) ? (remn >= 8 ? 16 : (remn > 0 ? remn * 2 : 0)) : 0;
            const long so = sz ? ((long)(k0 + krow) * ldb + col0 + no8) : 0;
            const uint32_t dst = sb + OFF_BH + krow * PITCH_B + (ch & 15) * 16;
            cp16(dst,                     Bh + so, sz);
            cp16(dst + (OFF_BL - OFF_BH), Bl + so, sz);
        }
    };

    auto computeChunk = [&](int buf) {
        const uint32_t sb = sbase + buf * STAGE_B;
        #pragma unroll
        for (int kb = 0; kb < 32; kb += 16) {
            uint32_t ahf[4][4], alf[4][4], bhf[8][2], blf[8][2];
            #pragma unroll
            for (int mt = 0; mt < 4; ++mt) {
                const uint32_t arow = wm * 64 + mt * 16 + (lane & 15);
                const uint32_t aoff = sb + arow * PITCH_A + (kb + ((lane >> 4) * 8)) * 2;
                ldsm4(ahf[mt], aoff);
                ldsm4(alf[mt], aoff + OFF_AL);
            }
            #pragma unroll
            for (int pair = 0; pair < 4; ++pair) {
                const uint32_t krow = kb + ((lane >> 3) & 1) * 8 + (lane & 7);
                const uint32_t ncol = wn * 64 + pair * 16 + (lane >> 4) * 8;
                const uint32_t boff = sb + OFF_BH + krow * PITCH_B + ncol * 2;
                uint32_t r4[4];
                ldsm4t(r4, boff);
                bhf[pair * 2][0] = r4[0]; bhf[pair * 2][1] = r4[1];
                bhf[pair * 2 + 1][0] = r4[2]; bhf[pair * 2 + 1][1] = r4[3];
                ldsm4t(r4, boff + (OFF_BL - OFF_BH));
                blf[pair * 2][0] = r4[0]; blf[pair * 2][1] = r4[1];
                blf[pair * 2 + 1][0] = r4[2]; blf[pair * 2 + 1][1] = r4[3];
            }
            #pragma unroll
            for (int mt = 0; mt < 4; ++mt)
                #pragma unroll
                for (int nt = 0; nt < 8; ++nt)
                    mma16816(acc[mt][nt], ahf[mt], bhf[nt]);
            #pragma unroll
            for (int mt = 0; mt < 4; ++mt)
                #pragma unroll
                for (int nt = 0; nt < 8; ++nt)
                    mma16816(acc[mt][nt], alf[mt], bhf[nt]);
            #pragma unroll
            for (int mt = 0; mt < 4; ++mt)
                #pragma unroll
                for (int nt = 0; nt < 8; ++nt)
                    mma16816(acc[mt][nt], ahf[mt], blf[nt]);
        }
    };

    issueStage(0, 0); cp_commit();
    if (nch > 1) { issueStage(1, 1); cp_commit(); }

    for (int c = 0; c < nch; ++c) {
        cp_wait((c + 2 <= nch) ? ((c + 1 < nch) ? 1 : 0) : 0);
        __syncthreads();
        if (c + 2 < nch) { issueStage(c + 2, (c + 2) % NSTAGE); cp_commit(); }
        computeChunk(c % NSTAGE);
    }

    // epilogue
    #pragma unroll
    for (int mt = 0; mt < 4; ++mt) {
        #pragma unroll
        for (int nt = 0; nt < 8; ++nt) {
            const int col = col0 + wn * 64 + nt * 8 + (lane & 3) * 2;
            if (col >= N) continue;
            #pragma unroll
            for (int half = 0; half < 2; ++half) {
                const int row = row0 + wm * 64 + mt * 16 + (lane >> 2) + half * 8;
                float2 v = make_float2(acc[mt][nt][half * 2], acc[mt][nt][half * 2 + 1]);
                if (d.bias) {
                    const float2 bv = *(const float2*)(d.bias + col);
                    v.x += bv.x; v.y += bv.y;
                }
                if (X) {
                    const float2 xv = *(const float2*)(X + (long)row * N + col);
                    v.x += xv.x; v.y += xv.y;
                }
                if (d.relu) { v.x = fmaxf(v.x, 0.f); v.y = fmaxf(v.y, 0.f); }
                int orow = row;
                if (d.rowmap) {
                    if (row < 2048) orow = ((row >> 3) << 4) + (row & 7);
                    else { const int a = row - 2048; orow = ((a >> 3) << 4) + 8 + (a & 7); }
                }
                if (Cf) *(float2*)(Cf + (long)orow * N + col) = v;
                if (Ch) {
                    __nv_bfloat16 hx, lx, hy, ly;
                    split1(v.x, hx, lx); split1(v.y, hy, ly);
                    const long o = (long)orow * d.ldo + col;
                    *(uint32_t*)(Ch + o) =
                        (uint32_t)__bfloat16_as_ushort(hx) | ((uint32_t)__bfloat16_as_ushort(hy) << 16);
                    *(uint32_t*)(Cl + o) =
                        (uint32_t)__bfloat16_as_ushort(lx) | ((uint32_t)__bfloat16_as_ushort(ly) << 16);
                }
            }
        }
    }
}

// ---------------------------------------------------------------------------
// Multi-job fp32 -> bf16 hi/lo plane convert (one launch)
// ---------------------------------------------------------------------------
#define NCVT 10
struct CvtJobs {
    const float* in[NCVT];
    __nv_bfloat16* h[NCVT];
    __nv_bfloat16* l[NCVT];
    long n[NCVT];
    int cols[NCVT], ldo[NCVT];
    int start[NCVT + 1];
};

__global__ __launch_bounds__(256)
void cvt_multi_kernel(CvtJobs J)
{
    const int bx = blockIdx.x;
    int j = 0;
    #pragma unroll
    for (int t = 0; t < NCVT - 1; ++t) if (bx >= J.start[t + 1]) j = t + 1;
    const long i = ((long)(bx - J.start[j]) * 256 + threadIdx.x) * 4;
    if (i >= J.n[j]) return;
    const float4 v = *(const float4*)(J.in[j] + i);
    long o;
    const int cols = J.cols[j], ldo = J.ldo[j];
    if (cols == ldo) o = i;
    else { const long r = i / cols; o = r * ldo + (int)(i - r * cols); }
    __nv_bfloat16 hh[4], ll[4];
    split1(v.x, hh[0], ll[0]); split1(v.y, hh[1], ll[1]);
    split1(v.z, hh[2], ll[2]); split1(v.w, hh[3], ll[3]);
    *(uint2*)(J.h[j] + o) = *(uint2*)hh;
    *(uint2*)(J.l[j] + o) = *(uint2*)ll;
}

__global__ __launch_bounds__(256)
void pack_qkv_kernel(const float* __restrict__ Wq, const float* __restrict__ Wk,
                     const float* __restrict__ Wv, const float* __restrict__ bq,
                     const float* __restrict__ bk, const float* __restrict__ bv,
                     __nv_bfloat16* __restrict__ h, __nv_bfloat16* __restrict__ l,
                     float* __restrict__ bias)
{
    const int idx = blockIdx.x * 256 + threadIdx.x;
    if (idx < 512 * 1536) {
        const int k = idx / 1536, n = idx % 1536, sel = n >> 9;
        const float* W = (sel == 0) ? Wq : (sel == 1) ? Wk : Wv;
        const float v = W[k * 512 + (n & 511)];
        __nv_bfloat16 hh, ll; split1(v, hh, ll);
        h[idx] = hh; l[idx] = ll;
    }
    if (idx < 1536) {
        const int sel = idx >> 9;
        const float* bb = (sel == 0) ? bq : (sel == 1) ? bk : bv;
        bias[idx] = bb[idx & 511];
    }
}

// b2[n] = be[n] + sum_k bp[k] * We[k][n]  (We top half, fp32 inputs)
__global__ __launch_bounds__(256)
void bias2_kernel(const float* __restrict__ bp, const float* __restrict__ We,
                  const float* __restrict__ be, float* __restrict__ b2)
{
    const int n = blockIdx.x * 256 + threadIdx.x;
    if (n >= 512) return;
    float s = be[n];
    for (int k = 0; k < 512; ++k) s = fmaf(bp[k], We[k * 512 + n], s);
    b2[n] = s;
}

// ---------------------------------------------------------------------------
// Segmented MHA, both paths in one launch (blockIdx.z = path)
// ---------------------------------------------------------------------------
__global__ __launch_bounds__(128)
void attn_mean_kernel(const float* __restrict__ QKV,
                      __nv_bfloat16* __restrict__ OmH, __nv_bfloat16* __restrict__ OmL)
{
    const int s = blockIdx.x, h = blockIdx.y, path = blockIdx.z, tid = threadIdx.x;
    __shared__ float qs[8][DH_ + 1], ks[8][DH_ + 1], vs[8][DH_ + 1];
    __shared__ float sc[8][9], wj[8];

    #pragma unroll
    for (int i = 0; i < 8; ++i) {
        int g;
        if (path == 0) g = s * 8 + i;
        else { const int t = s >> 3, j = s & 7; g = t * 64 + i * 8 + j; }
        const long off = (long)g * 1536 + h * DH_ + tid;
        qs[i][tid] = QKV[off];
        ks[i][tid] = QKV[off + 512];
        vs[i][tid] = QKV[off + 1024];
    }
    __syncthreads();

    if (tid < 64) {
        const int i = tid >> 3, j = tid & 7;
        float d = 0.f;
        #pragma unroll 16
        for (int k = 0; k < DH_; ++k) d = fmaf(qs[i][k], ks[j][k], d);
        sc[i][j] = d * 0.08838834764831845f;
    }
    __syncthreads();
    if (tid < 8) {
        const int i = tid;
        float m = -1e30f;
        #pragma unroll
        for (int j = 0; j < 8; ++j) m = fmaxf(m, sc[i][j]);
        float e[8], sum = 0.f;
        #pragma unroll
        for (int j = 0; j < 8; ++j) { e[j] = __expf(sc[i][j] - m); sum += e[j]; }
        const float inv = 1.f / sum;
        #pragma unroll
        for (int j = 0; j < 8; ++j) sc[i][j] = e[j] * inv;
    }
    __syncthreads();
    if (tid < 8) {
        const int j = tid;
        float w = 0.f;
        #pragma unroll
        for (int i = 0; i < 8; ++i) w += sc[i][j];
        wj[j] = w * 0.125f;
    }
    __syncthreads();
    float o = 0.f;
    #pragma unroll
    for (int j = 0; j < 8; ++j) o = fmaf(wj[j], vs[j][tid], o);

    const long off = (long)(path * SEGS + s) * 512 + h * DH_ + tid;
    __nv_bfloat16 hh, ll; split1(o, hh, ll);
    OmH[off] = hh; OmL[off] = ll;
}

// ---------------------------------------------------------------------------
// Host
// ---------------------------------------------------------------------------
#define SYM(p, s) cudaGetSymbolAddress((void**)&p, s)

struct Planes { __nv_bfloat16 *h, *l; };

static GDesc mkDesc(Planes A, int lda, long sAp, Planes Bp, int ldb, long sBp,
                    const float* bias, const float* X, long sX,
                    float* Cf, long sCf, Planes Co, int ldo, long sCo,
                    int M, int N, int K, int nb, int relu, int rowmap,
                    int* ctas)
{
    GDesc d;
    d.Ah = A.h; d.Al = A.l; d.Bh = Bp.h; d.Bl = Bp.l;
    d.bias = bias; d.X = X; d.Cf = Cf; d.Ch = Co.h; d.Cl = Co.l;
    d.sAp = sAp; d.sBp = sBp; d.sX = sX; d.sCf = sCf; d.sCo = sCo;
    d.lda = lda; d.ldb = ldb; d.ldo = ldo;
    d.M = M; d.N = N; d.K = K; d.relu = relu; d.rowmap = rowmap;
    d.gx = (N + 127) / 128; d.gy = M / 128;
    *ctas = d.gx * d.gy * nb;
    return d;
}

static inline void launchPair(const GDesc& a, int ca, const GDesc& b, int cb)
{
    mm2_kernel<<<ca + cb, 128, SMEM_DYN>>>(a, b, ca);
}
static inline void launchOne(const GDesc& a, int ca)
{
    mm2_kernel<<<ca, 128, SMEM_DYN>>>(a, a, ca);
}

extern "C" void kernel_launch(void* const* d_in, const int* in_sizes, int n_in,
                              void* d_out, int out_size)
{
    const float* Ao   = (const float*)d_in[0];
    const float* srco = (const float*)d_in[1];
    const float* Ar   = (const float*)d_in[2];
    const float* srcr = (const float*)d_in[3];
    const float* Wo1  = (const float*)d_in[4];
    const float* Wo2  = (const float*)d_in[5];
    const float* Wr1  = (const float*)d_in[6];
    const float* Wr2  = (const float*)d_in[7];
    const float* Wq   = (const float*)d_in[8];
    const float* bq   = (const float*)d_in[9];
    const float* Wk   = (const float*)d_in[10];
    const float* bk   = (const float*)d_in[11];
    const float* Wv   = (const float*)d_in[12];
    const float* bv   = (const float*)d_in[13];
    const float* Wp   = (const float*)d_in[14];
    const float* bp   = (const float*)d_in[15];
    const float* We   = (const float*)d_in[16];
    const float* be   = (const float*)d_in[17];
    float* out = (float*)d_out;

    cudaFuncSetAttribute(mm2_kernel, cudaFuncAttributeMaxDynamicSharedMemorySize, SMEM_DYN);

    float *T1, *T2, *T4, *QKV, *bqkv, *E, *b2;
    SYM(T1, g_T1); SYM(T2, g_T2); SYM(T4, g_T4);
    SYM(QKV, g_QKV); SYM(bqkv, g_bqkv); SYM(E, g_E); SYM(b2, g_b2);

    Planes PAo, PAr, PSo, PSr, PWo1, PWo2, PWr1, PWr2, PWqkv, PWp, PWe, PWf;
    Planes PT1, PH1o, PT2, PZ, PH1r, PT4, PGr, PGo, POm;
    SYM(PAo.h, pAo_h);   SYM(PAo.l, pAo_l);
    SYM(PAr.h, pAr_h);   SYM(PAr.l, pAr_l);
    SYM(PSo.h, pSo_h);   SYM(PSo.l, pSo_l);
    SYM(PSr.h, pSr_h);   SYM(PSr.l, pSr_l);
    SYM(PWo1.h, pWo1_h); SYM(PWo1.l, pWo1_l);
    SYM(PWo2.h, pWo2_h); SYM(PWo2.l, pWo2_l);
    SYM(PWr1.h, pWr1_h); SYM(PWr1.l, pWr1_l);
    SYM(PWr2.h, pWr2_h); SYM(PWr2.l, pWr2_l);
    SYM(PWqkv.h, pWqkv_h); SYM(PWqkv.l, pWqkv_l);
    SYM(PWp.h, pWp_h);   SYM(PWp.l, pWp_l);
    SYM(PWe.h, pWe_h);   SYM(PWe.l, pWe_l);
    SYM(PWf.h, pWf_h);   SYM(PWf.l, pWf_l);
    SYM(PT1.h, pT1_h);   SYM(PT1.l, pT1_l);
    SYM(PH1o.h, pH1o_h); SYM(PH1o.l, pH1o_l);
    SYM(PT2.h, pT2_h);   SYM(PT2.l, pT2_l);
    SYM(PZ.h, pZ_h);     SYM(PZ.l, pZ_l);
    SYM(PH1r.h, pH1r_h); SYM(PH1r.l, pH1r_l);
    SYM(PT4.h, pT4_h);   SYM(PT4.l, pT4_l);
    SYM(PGr.h, pGr_h);   SYM(PGr.l, pGr_l);
    SYM(PGo.h, pGo_h);   SYM(PGo.l, pGo_l);
    SYM(POm.h, pOm_h);   SYM(POm.l, pOm_l);

    const Planes NONE = {nullptr, nullptr};
    // We bottom half (rows 512..1023)
    Planes PWeBot = {PWe.h + 512 * 512, PWe.l + 512 * 512};

    // ---- one merged conversion launch ----
    {
        CvtJobs J;
        const float* ins[NCVT] = {Ar, srcr, srco, Ao, Wo1, Wo2, Wr1, Wr2, Wp, We};
        Planes      ps [NCVT] = {PAr, PSr, PSo, PAo, PWo1, PWo2, PWr1, PWr2, PWp, PWe};
        long        ns [NCVT] = {(long)8*2048*2048, (long)16384*300, (long)4096*1024,
                                 (long)8*512*512, (long)1024*1024, (long)1024*512,
                                 (long)300*1024, (long)1024*512, (long)512*512,
                                 (long)1024*512};
        int         cs [NCVT] = {2048, 300, 1024, 512, 1024, 512, 1024, 512, 512, 512};
        int         ld [NCVT] = {2048, 304, 1024, 512, 1024, 512, 1024, 512, 512, 512};
        int cum = 0;
        for (int j = 0; j < NCVT; ++j) {
            J.in[j] = ins[j]; J.h[j] = ps[j].h; J.l[j] = ps[j].l;
            J.n[j] = ns[j]; J.cols[j] = cs[j]; J.ldo[j] = ld[j];
            J.start[j] = cum;
            cum += (int)((ns[j] + 1023) / 1024);
        }
        J.start[NCVT] = cum;
        cvt_multi_kernel<<<cum, 256>>>(J);
    }
    pack_qkv_kernel<<<(512 * 1536 + 255) / 256, 256>>>(Wq, Wk, Wv, bq, bk, bv,
                                                       PWqkv.h, PWqkv.l, bqkv);
    bias2_kernel<<<2, 256>>>(bp, We, be, b2);

    int c0, c1;
    // ---- pair 1: Z = Ar@srcr + srcr  ||  T1 = srco@Wo1 ----
    {
        GDesc dZ = mkDesc(PAr, 2048, (long)2048*2048, PSr, 304, (long)2048*304,
                          nullptr, srcr, (long)2048*300, nullptr, 0,
                          PZ, 304, (long)2048*304, 2048, 300, 2048, B_, 0, 0, &c0);
        GDesc dT1 = mkDesc(PSo, 1024, 0, PWo1, 1024, 0, nullptr, nullptr, 0,
                           T1, 0, PT1, 1024, 0, ROWS_O, 1024, 1024, 1, 0, 0, &c1);
        launchPair(dZ, c0, dT1, c1);
    }
    // ---- pair 2: H1r = relu(Z@Wr1)  ||  H1o = relu(Ao@T1 + T1) ----
    {
        GDesc dH1r = mkDesc(PZ, 304, 0, PWr1, 1024, 0, nullptr, nullptr, 0,
                            nullptr, 0, PH1r, 1024, 0, TOK, 1024, 300, 1, 1, 0, &c0);
        GDesc dH1o = mkDesc(PAo, 512, (long)512*512, PT1, 1024, (long)512*1024,
                            nullptr, T1, (long)512*1024, nullptr, 0,
                            PH1o, 1024, (long)512*1024, 512, 1024, 512, B_, 1, 0, &c1);
        launchPair(dH1r, c0, dH1o, c1);
    }
    // ---- pair 3: T4 = H1r@Wr2  ||  T2 = H1o@Wo2 ----
    {
        GDesc dT4 = mkDesc(PH1r, 1024, 0, PWr2, 512, 0, nullptr, nullptr, 0,
                           T4, 0, PT4, 512, 0, TOK, 512, 1024, 1, 0, 0, &c0);
        GDesc dT2 = mkDesc(PH1o, 1024, 0, PWo2, 512, 0, nullptr, nullptr, 0,
                           T2, 0, PT2, 512, 0, ROWS_O, 512, 1024, 1, 0, 0, &c1);
        launchPair(dT4, c0, dT2, c1);
    }
    // ---- pair 4: Gr = relu(Ar@T4 + T4)  ||  Go = relu(Ao@T2 + T2) -> planes ----
    {
        GDesc dGr = mkDesc(PAr, 2048, (long)2048*2048, PT4, 512, (long)2048*512,
                           nullptr, T4, (long)2048*512, nullptr, 0,
                           PGr, 512, (long)2048*512, 2048, 512, 2048, B_, 1, 0, &c0);
        GDesc dGo = mkDesc(PAo, 512, (long)512*512, PT2, 512, (long)512*512,
                           nullptr, T2, (long)512*512, nullptr, 0,
                           PGo, 512, (long)512*512, 512, 512, 512, B_, 1, 0, &c1);
        launchPair(dGr, c0, dGo, c1);
    }
    // ---- pair 5: QKV (N=1536)  ||  Wf = Wp@We_top (hides in QKV tail) ----
    {
        GDesc dQKV = mkDesc(PGr, 512, 0, PWqkv, 1536, 0, bqkv, nullptr, 0,
                            QKV, 0, NONE, 0, 0, TOK, 1536, 512, 1, 0, 0, &c0);
        GDesc dWf = mkDesc(PWp, 512, 0, PWe, 512, 0, nullptr, nullptr, 0,
                           nullptr, 0, PWf, 512, 0, 512, 512, 512, 1, 0, 0, &c1);
        launchPair(dQKV, c0, dWf, c1);
    }
    // ---- attention ----
    {
        dim3 grid(SEGS, H_, 2);
        attn_mean_kernel<<<grid, 128>>>(QKV, POm.h, POm.l);
    }
    // ---- E = Om@Wf + b2 (row-permuted fp32) ----
    {
        GDesc dE = mkDesc(POm, 512, 0, PWf, 512, 0, b2, nullptr, 0,
                          E, 0, NONE, 0, 0, 4096, 512, 512, 1, 0, 1, &c0);
        launchOne(dE, c0);
    }
    // ---- final: out = Go@We_bot + E ----
    {
        GDesc dF = mkDesc(PGo, 512, 0, PWeBot, 512, 0, nullptr, E, 0,
                          out, 0, NONE, 0, 0, OUT_ROWS, 512, 512, 1, 0, 0, &c0);
        launchOne(dF, c0);
    }
}

// round 17
// speedup vs baseline: 1.4793x; 1.0163x over previous
#include <cuda_runtime.h>
#include <cuda_bf16.h>
#include <cstdint>

// ---------------------------------------------------------------------------
// Problem constants: B=8, NT=32, NO=8, C=512, VD=1024, RD=300, H=4
// ---------------------------------------------------------------------------
#define B_  8
#define C_  512
#define H_  4
#define DH_ 128
#define SEGS 2048
#define TOK  16384
#define ROWS_O 4096
#define OUT_ROWS 4096

// ---------------------------------------------------------------------------
// fp32 scratch
// ---------------------------------------------------------------------------
__device__ float g_T1 [ROWS_O * 1024];
__device__ float g_T2 [ROWS_O * 512];
__device__ float g_T4 [TOK * 512];
__device__ float g_QKV[TOK * 1536];
__device__ float g_bqkv[1536];
__device__ float g_b2 [512];            // bp@We_top + be

// bf16 hi/lo plane scratch
__device__ __nv_bfloat16 pAo_h [8*512*512],    pAo_l [8*512*512];
__device__ __nv_bfloat16 pAr_h [8*2048*2048],  pAr_l [8*2048*2048];
__device__ __nv_bfloat16 pSo_h [4096*1024],    pSo_l [4096*1024];
__device__ __nv_bfloat16 pSr_h [16384*304],    pSr_l [16384*304];   // ld=304
__device__ __nv_bfloat16 pWo1_h[1024*1024],    pWo1_l[1024*1024];
__device__ __nv_bfloat16 pWo2_h[1024*512],     pWo2_l[1024*512];
__device__ __nv_bfloat16 pWr1_h[300*1024],     pWr1_l[300*1024];
__device__ __nv_bfloat16 pWr2_h[1024*512],     pWr2_l[1024*512];
__device__ __nv_bfloat16 pWqkv_h[512*1536],    pWqkv_l[512*1536];
__device__ __nv_bfloat16 pWp_h [512*512],      pWp_l [512*512];
__device__ __nv_bfloat16 pWe_h [1024*512],     pWe_l [1024*512];
__device__ __nv_bfloat16 pWcat_h[1024*512],    pWcat_l[1024*512];   // [We_bot ; Wf]
__device__ __nv_bfloat16 pT1_h [4096*1024],    pT1_l [4096*1024];
__device__ __nv_bfloat16 pH1o_h[4096*1024],    pH1o_l[4096*1024];
__device__ __nv_bfloat16 pT2_h [4096*512],     pT2_l [4096*512];
__device__ __nv_bfloat16 pZ_h  [16384*304],    pZ_l  [16384*304];   // ld=304
__device__ __nv_bfloat16 pH1r_h[16384*1024],   pH1r_l[16384*1024];
__device__ __nv_bfloat16 pT4_h [16384*512],    pT4_l [16384*512];
__device__ __nv_bfloat16 pGr_h [16384*512],    pGr_l [16384*512];
__device__ __nv_bfloat16 pAll_h[4096*1024],    pAll_l[4096*1024];   // [Go | Om_perm]

// ---------------------------------------------------------------------------
// helpers
// ---------------------------------------------------------------------------
__device__ __forceinline__ uint32_t smem_u32(const void* p) {
    uint32_t a;
    asm("{ .reg .u64 t; cvta.to.shared.u64 t, %1; cvt.u32.u64 %0, t; }"
        : "=r"(a) : "l"(p));
    return a;
}
__device__ __forceinline__ void cp16(uint32_t dst, const void* src, int sz) {
    asm volatile("cp.async.cg.shared.global [%0], [%1], 16, %2;"
                 :: "r"(dst), "l"(src), "r"(sz));
}
__device__ __forceinline__ void cp_commit() {
    asm volatile("cp.async.commit_group;");
}
__device__ __forceinline__ void cp_wait(int pend) {
    if (pend >= 1) asm volatile("cp.async.wait_group 1;");
    else           asm volatile("cp.async.wait_group 0;");
}
__device__ __forceinline__ void ldsm4(uint32_t* r, uint32_t addr) {
    asm volatile("ldmatrix.sync.aligned.m8n8.x4.shared.b16 {%0,%1,%2,%3}, [%4];"
                 : "=r"(r[0]), "=r"(r[1]), "=r"(r[2]), "=r"(r[3]) : "r"(addr));
}
__device__ __forceinline__ void ldsm4t(uint32_t* r, uint32_t addr) {
    asm volatile("ldmatrix.sync.aligned.m8n8.x4.trans.shared.b16 {%0,%1,%2,%3}, [%4];"
                 : "=r"(r[0]), "=r"(r[1]), "=r"(r[2]), "=r"(r[3]) : "r"(addr));
}
__device__ __forceinline__ void mma16816(float* d, const uint32_t* a, const uint32_t* b) {
    asm volatile(
        "mma.sync.aligned.m16n8k16.row.col.f32.bf16.bf16.f32 "
        "{%0,%1,%2,%3}, {%4,%5,%6,%7}, {%8,%9}, {%0,%1,%2,%3};"
        : "+f"(d[0]), "+f"(d[1]), "+f"(d[2]), "+f"(d[3])
        : "r"(a[0]), "r"(a[1]), "r"(a[2]), "r"(a[3]), "r"(b[0]), "r"(b[1]));
}
__device__ __forceinline__ void split1(float x, __nv_bfloat16& h, __nv_bfloat16& l) {
    h = __float2bfloat16(x);
    l = __float2bfloat16(x - __bfloat162float(h));
}

// ---------------------------------------------------------------------------
// SMEM stage layout (bytes)
// ---------------------------------------------------------------------------
#define PITCH_A 80
#define PITCH_B 272
#define OFF_AL 10240
#define OFF_BH 20480
#define OFF_BL 29184
#define STAGE_B 37888
#define NSTAGE 3
#define SMEM_DYN (NSTAGE * STAGE_B)     // 113664 -> 2 CTAs/SM

// ---------------------------------------------------------------------------
// GEMM descriptor
// ---------------------------------------------------------------------------
struct GDesc {
    const __nv_bfloat16 *Ah, *Al, *Bh, *Bl;
    const float *bias, *X;
    float* Cf;
    __nv_bfloat16 *Ch, *Cl;
    long sAp, sBp, sX, sCf, sCo;
    int lda, ldb, ldo;
    int M, N, K, relu;
    int gx, gy;
};

// ---------------------------------------------------------------------------
// HMMA bf16-split GEMM v8: R12 schedule + register double-buffered B frags.
// 128 threads (2x2 warps, 64x64 warp tile), 128x128 CTA tile, 3-stage pipeline.
// ---------------------------------------------------------------------------
__global__ __launch_bounds__(128, 2)
void mm2_kernel(GDesc d0, GDesc d1, int boundary)
{
    extern __shared__ char smem[];
    const uint32_t sbase = smem_u32(smem);

    const bool second = ((int)blockIdx.x >= boundary);
    const GDesc& d = second ? d1 : d0;
    const int local = (int)blockIdx.x - (second ? boundary : 0);
    const int gxy = d.gx * d.gy;
    const int bz  = local / gxy;
    const int rem = local - bz * gxy;
    const int by  = rem / d.gx;
    const int bxx = rem - by * d.gx;

    const __nv_bfloat16* Ah = d.Ah + (long)bz * d.sAp;
    const __nv_bfloat16* Al = d.Al + (long)bz * d.sAp;
    const __nv_bfloat16* Bh = d.Bh + (long)bz * d.sBp;
    const __nv_bfloat16* Bl = d.Bl + (long)bz * d.sBp;
    float* Cf = d.Cf ? (d.Cf + (long)bz * d.sCf) : nullptr;
    __nv_bfloat16* Ch = d.Ch ? (d.Ch + (long)bz * d.sCo) : nullptr;
    __nv_bfloat16* Cl = d.Cl ? (d.Cl + (long)bz * d.sCo) : nullptr;
    const float* X = d.X ? (d.X + (long)bz * d.sX) : nullptr;
    const int lda = d.lda, ldb = d.ldb, N = d.N, K = d.K;

    const int tid  = threadIdx.x;        // 0..127
    const int wid  = tid >> 5;           // 0..3
    const int lane = tid & 31;
    const int row0 = by * 128;
    const int col0 = bxx * 128;
    const int wm = wid >> 1;             // rows wm*64
    const int wn = wid & 1;              // cols wn*64

    float acc[4][8][4];
    #pragma unroll
    for (int mt = 0; mt < 4; ++mt)
        #pragma unroll
        for (int nt = 0; nt < 8; ++nt)
            #pragma unroll
            for (int e = 0; e < 4; ++e) acc[mt][nt][e] = 0.f;

    const int nch = (K + 31) >> 5;

    auto issueStage = [&](int c, int buf) {
        const int k0 = c << 5;
        const uint32_t sb = sbase + buf * STAGE_B;
        #pragma unroll
        for (int i = 0; i < 4; ++i) {
            const int ch  = tid + i * 128;
            const int row = ch >> 2;
            const int o8  = (ch & 3) * 8;
            const int rem2 = K - (k0 + o8);
            const int sz  = rem2 >= 8 ? 16 : (rem2 > 0 ? rem2 * 2 : 0);
            const long so = (long)(row0 + row) * lda + (sz ? (k0 + o8) : 0);
            const uint32_t dst = sb + row * PITCH_A + (ch & 3) * 16;
            cp16(dst,          Ah + so, sz);
            cp16(dst + OFF_AL, Al + so, sz);
        }
        #pragma unroll
        for (int i = 0; i < 4; ++i) {
            const int ch   = tid + i * 128;
            const int krow = ch >> 4;
            const int no8  = (ch & 15) * 8;
            const int remn = N - (col0 + no8);
            int sz = (k0 + krow < K) ? (remn >= 8 ? 16 : (remn > 0 ? remn * 2 : 0)) : 0;
            const long so = sz ? ((long)(k0 + krow) * ldb + col0 + no8) : 0;
            const uint32_t dst = sb + OFF_BH + krow * PITCH_B + (ch & 15) * 16;
            cp16(dst,                     Bh + so, sz);
            cp16(dst + (OFF_BL - OFF_BH), Bl + so, sz);
        }
    };

    // load B fragments (both planes) for one 16-k substep
    auto loadB = [&](uint32_t sb, int kb, uint32_t bhf[8][2], uint32_t blf[8][2]) {
        #pragma unroll
        for (int pair = 0; pair < 4; ++pair) {
            const uint32_t krow = kb + ((lane >> 3) & 1) * 8 + (lane & 7);
            const uint32_t ncol = wn * 64 + pair * 16 + (lane >> 4) * 8;
            const uint32_t boff = sb + OFF_BH + krow * PITCH_B + ncol * 2;
            uint32_t r4[4];
            ldsm4t(r4, boff);
            bhf[pair * 2][0] = r4[0]; bhf[pair * 2][1] = r4[1];
            bhf[pair * 2 + 1][0] = r4[2]; bhf[pair * 2 + 1][1] = r4[3];
            ldsm4t(r4, boff + (OFF_BL - OFF_BH));
            blf[pair * 2][0] = r4[0]; blf[pair * 2][1] = r4[1];
            blf[pair * 2 + 1][0] = r4[2]; blf[pair * 2 + 1][1] = r4[3];
        }
    };

    auto computeChunk = [&](int buf) {
        const uint32_t sb = sbase + buf * STAGE_B;
        uint32_t bh0[8][2], bl0[8][2], bh1[8][2], bl1[8][2];
        loadB(sb, 0, bh0, bl0);
        // substep 0 (B1 loads kicked off under mt0's MMAs)
        #pragma unroll
        for (int mt = 0; mt < 4; ++mt) {
            uint32_t ahf[4], alf[4];
            const uint32_t arow = wm * 64 + mt * 16 + (lane & 15);
            const uint32_t aoff = sb + arow * PITCH_A + ((lane >> 4) * 8) * 2;
            ldsm4(ahf, aoff);
            ldsm4(alf, aoff + OFF_AL);
            if (mt == 0) loadB(sb, 16, bh1, bl1);
            #pragma unroll
            for (int nt = 0; nt < 8; ++nt) mma16816(acc[mt][nt], ahf, bh0[nt]);
            #pragma unroll
            for (int nt = 0; nt < 8; ++nt) mma16816(acc[mt][nt], alf, bh0[nt]);
            #pragma unroll
            for (int nt = 0; nt < 8; ++nt) mma16816(acc[mt][nt], ahf, bl0[nt]);
        }
        // substep 1
        #pragma unroll
        for (int mt = 0; mt < 4; ++mt) {
            uint32_t ahf[4], alf[4];
            const uint32_t arow = wm * 64 + mt * 16 + (lane & 15);
            const uint32_t aoff = sb + arow * PITCH_A + (16 + (lane >> 4) * 8) * 2;
            ldsm4(ahf, aoff);
            ldsm4(alf, aoff + OFF_AL);
            #pragma unroll
            for (int nt = 0; nt < 8; ++nt) mma16816(acc[mt][nt], ahf, bh1[nt]);
            #pragma unroll
            for (int nt = 0; nt < 8; ++nt) mma16816(acc[mt][nt], alf, bh1[nt]);
            #pragma unroll
            for (int nt = 0; nt < 8; ++nt) mma16816(acc[mt][nt], ahf, bl1[nt]);
        }
    };

    issueStage(0, 0); cp_commit();
    if (nch > 1) { issueStage(1, 1); cp_commit(); }

    for (int c = 0; c < nch; ++c) {
        cp_wait((c + 2 <= nch) ? ((c + 1 < nch) ? 1 : 0) : 0);
        __syncthreads();
        if (c + 2 < nch) { issueStage(c + 2, (c + 2) % NSTAGE); cp_commit(); }
        computeChunk(c % NSTAGE);
    }

    // epilogue
    #pragma unroll
    for (int mt = 0; mt < 4; ++mt) {
        #pragma unroll
        for (int nt = 0; nt < 8; ++nt) {
            const int col = col0 + wn * 64 + nt * 8 + (lane & 3) * 2;
            if (col >= N) continue;
            #pragma unroll
            for (int half = 0; half < 2; ++half) {
                const int row = row0 + wm * 64 + mt * 16 + (lane >> 2) + half * 8;
                float2 v = make_float2(acc[mt][nt][half * 2], acc[mt][nt][half * 2 + 1]);
                if (d.bias) {
                    const float2 bv = *(const float2*)(d.bias + col);
                    v.x += bv.x; v.y += bv.y;
                }
                if (X) {
                    const float2 xv = *(const float2*)(X + (long)row * N + col);
                    v.x += xv.x; v.y += xv.y;
                }
                if (d.relu) { v.x = fmaxf(v.x, 0.f); v.y = fmaxf(v.y, 0.f); }
                if (Cf) *(float2*)(Cf + (long)row * N + col) = v;
                if (Ch) {
                    __nv_bfloat16 hx, lx, hy, ly;
                    split1(v.x, hx, lx); split1(v.y, hy, ly);
                    const long o = (long)row * d.ldo + col;
                    *(uint32_t*)(Ch + o) =
                        (uint32_t)__bfloat16_as_ushort(hx) | ((uint32_t)__bfloat16_as_ushort(hy) << 16);
                    *(uint32_t*)(Cl + o) =
                        (uint32_t)__bfloat16_as_ushort(lx) | ((uint32_t)__bfloat16_as_ushort(ly) << 16);
                }
            }
        }
    }
}

// ---------------------------------------------------------------------------
// Multi-job fp32 -> bf16 hi/lo plane convert (one launch)
// ---------------------------------------------------------------------------
#define NCVT 11
struct CvtJobs {
    const float* in[NCVT];
    __nv_bfloat16* h[NCVT];
    __nv_bfloat16* l[NCVT];
    long n[NCVT];
    int cols[NCVT], ldo[NCVT];
    int start[NCVT + 1];
};

__global__ __launch_bounds__(256)
void cvt_multi_kernel(CvtJobs J)
{
    const int bx = blockIdx.x;
    int j = 0;
    #pragma unroll
    for (int t = 0; t < NCVT - 1; ++t) if (bx >= J.start[t + 1]) j = t + 1;
    const long i = ((long)(bx - J.start[j]) * 256 + threadIdx.x) * 4;
    if (i >= J.n[j]) return;
    const float4 v = *(const float4*)(J.in[j] + i);
    long o;
    const int cols = J.cols[j], ldo = J.ldo[j];
    if (cols == ldo) o = i;
    else { const long r = i / cols; o = r * ldo + (int)(i - r * cols); }
    __nv_bfloat16 hh[4], ll[4];
    split1(v.x, hh[0], ll[0]); split1(v.y, hh[1], ll[1]);
    split1(v.z, hh[2], ll[2]); split1(v.w, hh[3], ll[3]);
    *(uint2*)(J.h[j] + o) = *(uint2*)hh;
    *(uint2*)(J.l[j] + o) = *(uint2*)ll;
}

__global__ __launch_bounds__(256)
void pack_qkv_kernel(const float* __restrict__ Wq, const float* __restrict__ Wk,
                     const float* __restrict__ Wv, const float* __restrict__ bq,
                     const float* __restrict__ bk, const float* __restrict__ bv,
                     __nv_bfloat16* __restrict__ h, __nv_bfloat16* __restrict__ l,
                     float* __restrict__ bias)
{
    const int idx = blockIdx.x * 256 + threadIdx.x;
    if (idx < 512 * 1536) {
        const int k = idx / 1536, n = idx % 1536, sel = n >> 9;
        const float* W = (sel == 0) ? Wq : (sel == 1) ? Wk : Wv;
        const float v = W[k * 512 + (n & 511)];
        __nv_bfloat16 hh, ll; split1(v, hh, ll);
        h[idx] = hh; l[idx] = ll;
    }
    if (idx < 1536) {
        const int sel = idx >> 9;
        const float* bb = (sel == 0) ? bq : (sel == 1) ? bk : bv;
        bias[idx] = bb[idx & 511];
    }
}

// b2[n] = be[n] + sum_k bp[k] * We[k][n]  (We top half)
__global__ __launch_bounds__(256)
void bias2_kernel(const float* __restrict__ bp, const float* __restrict__ We,
                  const float* __restrict__ be, float* __restrict__ b2)
{
    const int n = blockIdx.x * 256 + threadIdx.x;
    if (n >= 512) return;
    float s = be[n];
    for (int k = 0; k < 512; ++k) s = fmaf(bp[k], We[k * 512 + n], s);
    b2[n] = s;
}

// ---------------------------------------------------------------------------
// Segmented MHA; writes permuted rows directly into pAll cols 512..1023
// ---------------------------------------------------------------------------
__global__ __launch_bounds__(128)
void attn_mean_kernel(const float* __restrict__ QKV,
                      __nv_bfloat16* __restrict__ AllH, __nv_bfloat16* __restrict__ AllL)
{
    const int s = blockIdx.x, h = blockIdx.y, path = blockIdx.z, tid = threadIdx.x;
    __shared__ float qs[8][DH_ + 1], ks[8][DH_ + 1], vs[8][DH_ + 1];
    __shared__ float sc[8][9], wj[8];

    #pragma unroll
    for (int i = 0; i < 8; ++i) {
        int g;
        if (path == 0) g = s * 8 + i;
        else { const int t = s >> 3, j = s & 7; g = t * 64 + i * 8 + j; }
        const long off = (long)g * 1536 + h * DH_ + tid;
        qs[i][tid] = QKV[off];
        ks[i][tid] = QKV[off + 512];
        vs[i][tid] = QKV[off + 1024];
    }
    __syncthreads();

    if (tid < 64) {
        const int i = tid >> 3, j = tid & 7;
        float d = 0.f;
        #pragma unroll 16
        for (int k = 0; k < DH_; ++k) d = fmaf(qs[i][k], ks[j][k], d);
        sc[i][j] = d * 0.08838834764831845f;
    }
    __syncthreads();
    if (tid < 8) {
        const int i = tid;
        float m = -1e30f;
        #pragma unroll
        for (int j = 0; j < 8; ++j) m = fmaxf(m, sc[i][j]);
        float e[8], sum = 0.f;
        #pragma unroll
        for (int j = 0; j < 8; ++j) { e[j] = __expf(sc[i][j] - m); sum += e[j]; }
        const float inv = 1.f / sum;
        #pragma unroll
        for (int j = 0; j < 8; ++j) sc[i][j] = e[j] * inv;
    }
    __syncthreads();
    if (tid < 8) {
        const int j = tid;
        float w = 0.f;
        #pragma unroll
        for (int i = 0; i < 8; ++i) w += sc[i][j];
        wj[j] = w * 0.125f;
    }
    __syncthreads();
    float o = 0.f;
    #pragma unroll
    for (int j = 0; j < 8; ++j) o = fmaf(wj[j], vs[j][tid], o);

    // permuted row: t*16 + path*8 + r ; cols 512..1023 of pAll (ld 1024)
    const int t = s >> 3, r = s & 7;
    const int row = t * 16 + path * 8 + r;
    const long off = (long)row * 1024 + 512 + h * DH_ + tid;
    __nv_bfloat16 hh, ll; split1(o, hh, ll);
    AllH[off] = hh; AllL[off] = ll;
}

// ---------------------------------------------------------------------------
// Host
// ---------------------------------------------------------------------------
#define SYM(p, s) cudaGetSymbolAddress((void**)&p, s)

struct Planes { __nv_bfloat16 *h, *l; };

static GDesc mkDesc(Planes A, int lda, long sAp, Planes Bp, int ldb, long sBp,
                    const float* bias, const float* X, long sX,
                    float* Cf, long sCf, Planes Co, int ldo, long sCo,
                    int M, int N, int K, int nb, int relu, int* ctas)
{
    GDesc d;
    d.Ah = A.h; d.Al = A.l; d.Bh = Bp.h; d.Bl = Bp.l;
    d.bias = bias; d.X = X; d.Cf = Cf; d.Ch = Co.h; d.Cl = Co.l;
    d.sAp = sAp; d.sBp = sBp; d.sX = sX; d.sCf = sCf; d.sCo = sCo;
    d.lda = lda; d.ldb = ldb; d.ldo = ldo;
    d.M = M; d.N = N; d.K = K; d.relu = relu;
    d.gx = (N + 127) / 128; d.gy = M / 128;
    *ctas = d.gx * d.gy * nb;
    return d;
}

static inline void launchPair(const GDesc& a, int ca, const GDesc& b, int cb)
{
    mm2_kernel<<<ca + cb, 128, SMEM_DYN>>>(a, b, ca);
}
static inline void launchOne(const GDesc& a, int ca)
{
    mm2_kernel<<<ca, 128, SMEM_DYN>>>(a, a, ca);
}

extern "C" void kernel_launch(void* const* d_in, const int* in_sizes, int n_in,
                              void* d_out, int out_size)
{
    const float* Ao   = (const float*)d_in[0];
    const float* srco = (const float*)d_in[1];
    const float* Ar   = (const float*)d_in[2];
    const float* srcr = (const float*)d_in[3];
    const float* Wo1  = (const float*)d_in[4];
    const float* Wo2  = (const float*)d_in[5];
    const float* Wr1  = (const float*)d_in[6];
    const float* Wr2  = (const float*)d_in[7];
    const float* Wq   = (const float*)d_in[8];
    const float* bq   = (const float*)d_in[9];
    const float* Wk   = (const float*)d_in[10];
    const float* bk   = (const float*)d_in[11];
    const float* Wv   = (const float*)d_in[12];
    const float* bv   = (const float*)d_in[13];
    const float* Wp   = (const float*)d_in[14];
    const float* bp   = (const float*)d_in[15];
    const float* We   = (const float*)d_in[16];
    const float* be   = (const float*)d_in[17];
    float* out = (float*)d_out;

    cudaFuncSetAttribute(mm2_kernel, cudaFuncAttributeMaxDynamicSharedMemorySize, SMEM_DYN);

    float *T1, *T2, *T4, *QKV, *bqkv, *b2;
    SYM(T1, g_T1); SYM(T2, g_T2); SYM(T4, g_T4);
    SYM(QKV, g_QKV); SYM(bqkv, g_bqkv); SYM(b2, g_b2);

    Planes PAo, PAr, PSo, PSr, PWo1, PWo2, PWr1, PWr2, PWqkv, PWp, PWe, PWcat;
    Planes PT1, PH1o, PT2, PZ, PH1r, PT4, PGr, PAll;
    SYM(PAo.h, pAo_h);   SYM(PAo.l, pAo_l);
    SYM(PAr.h, pAr_h);   SYM(PAr.l, pAr_l);
    SYM(PSo.h, pSo_h);   SYM(PSo.l, pSo_l);
    SYM(PSr.h, pSr_h);   SYM(PSr.l, pSr_l);
    SYM(PWo1.h, pWo1_h); SYM(PWo1.l, pWo1_l);
    SYM(PWo2.h, pWo2_h); SYM(PWo2.l, pWo2_l);
    SYM(PWr1.h, pWr1_h); SYM(PWr1.l, pWr1_l);
    SYM(PWr2.h, pWr2_h); SYM(PWr2.l, pWr2_l);
    SYM(PWqkv.h, pWqkv_h); SYM(PWqkv.l, pWqkv_l);
    SYM(PWp.h, pWp_h);   SYM(PWp.l, pWp_l);
    SYM(PWe.h, pWe_h);   SYM(PWe.l, pWe_l);
    SYM(PWcat.h, pWcat_h); SYM(PWcat.l, pWcat_l);
    SYM(PT1.h, pT1_h);   SYM(PT1.l, pT1_l);
    SYM(PH1o.h, pH1o_h); SYM(PH1o.l, pH1o_l);
    SYM(PT2.h, pT2_h);   SYM(PT2.l, pT2_l);
    SYM(PZ.h, pZ_h);     SYM(PZ.l, pZ_l);
    SYM(PH1r.h, pH1r_h); SYM(PH1r.l, pH1r_l);
    SYM(PT4.h, pT4_h);   SYM(PT4.l, pT4_l);
    SYM(PGr.h, pGr_h);   SYM(PGr.l, pGr_l);
    SYM(PAll.h, pAll_h); SYM(PAll.l, pAll_l);

    const Planes NONE = {nullptr, nullptr};
    Planes PWcatBot = {PWcat.h + 512 * 512, PWcat.l + 512 * 512};  // Wf target

    // ---- one merged conversion launch (incl. We_bot -> Wcat rows 0..511) ----
    {
        CvtJobs J;
        const float* ins[NCVT] = {Ar, srcr, srco, Ao, Wo1, Wo2, Wr1, Wr2, Wp, We,
                                  We + 512 * 512};
        Planes      ps [NCVT] = {PAr, PSr, PSo, PAo, PWo1, PWo2, PWr1, PWr2, PWp, PWe,
                                 PWcat};
        long        ns [NCVT] = {(long)8*2048*2048, (long)16384*300, (long)4096*1024,
                                 (long)8*512*512, (long)1024*1024, (long)1024*512,
                                 (long)300*1024, (long)1024*512, (long)512*512,
                                 (long)1024*512, (long)512*512};
        int         cs [NCVT] = {2048, 300, 1024, 512, 1024, 512, 1024, 512, 512, 512, 512};
        int         ld [NCVT] = {2048, 304, 1024, 512, 1024, 512, 1024, 512, 512, 512, 512};
        int cum = 0;
        for (int j = 0; j < NCVT; ++j) {
            J.in[j] = ins[j]; J.h[j] = ps[j].h; J.l[j] = ps[j].l;
            J.n[j] = ns[j]; J.cols[j] = cs[j]; J.ldo[j] = ld[j];
            J.start[j] = cum;
            cum += (int)((ns[j] + 1023) / 1024);
        }
        J.start[NCVT] = cum;
        cvt_multi_kernel<<<cum, 256>>>(J);
    }
    pack_qkv_kernel<<<(512 * 1536 + 255) / 256, 256>>>(Wq, Wk, Wv, bq, bk, bv,
                                                       PWqkv.h, PWqkv.l, bqkv);
    bias2_kernel<<<2, 256>>>(bp, We, be, b2);

    int c0, c1;
    // ---- pair 1: Z = Ar@srcr + srcr  ||  T1 = srco@Wo1 ----
    {
        GDesc dZ = mkDesc(PAr, 2048, (long)2048*2048, PSr, 304, (long)2048*304,
                          nullptr, srcr, (long)2048*300, nullptr, 0,
                          PZ, 304, (long)2048*304, 2048, 300, 2048, B_, 0, &c0);
        GDesc dT1 = mkDesc(PSo, 1024, 0, PWo1, 1024, 0, nullptr, nullptr, 0,
                           T1, 0, PT1, 1024, 0, ROWS_O, 1024, 1024, 1, 0, &c1);
        launchPair(dZ, c0, dT1, c1);
    }
    // ---- pair 2: H1r = relu(Z@Wr1)  ||  H1o = relu(Ao@T1 + T1) ----
    {
        GDesc dH1r = mkDesc(PZ, 304, 0, PWr1, 1024, 0, nullptr, nullptr, 0,
                            nullptr, 0, PH1r, 1024, 0, TOK, 1024, 300, 1, 1, &c0);
        GDesc dH1o = mkDesc(PAo, 512, (long)512*512, PT1, 1024, (long)512*1024,
                            nullptr, T1, (long)512*1024, nullptr, 0,
                            PH1o, 1024, (long)512*1024, 512, 1024, 512, B_, 1, &c1);
        launchPair(dH1r, c0, dH1o, c1);
    }
    // ---- pair 3: T4 = H1r@Wr2  ||  T2 = H1o@Wo2 ----
    {
        GDesc dT4 = mkDesc(PH1r, 1024, 0, PWr2, 512, 0, nullptr, nullptr, 0,
                           T4, 0, PT4, 512, 0, TOK, 512, 1024, 1, 0, &c0);
        GDesc dT2 = mkDesc(PH1o, 1024, 0, PWo2, 512, 0, nullptr, nullptr, 0,
                           T2, 0, PT2, 512, 0, ROWS_O, 512, 1024, 1, 0, &c1);
        launchPair(dT4, c0, dT2, c1);
    }
    // ---- pair 4: Gr = relu(Ar@T4 + T4)  ||  Go -> pAll cols 0..511 ----
    {
        GDesc dGr = mkDesc(PAr, 2048, (long)2048*2048, PT4, 512, (long)2048*512,
                           nullptr, T4, (long)2048*512, nullptr, 0,
                           PGr, 512, (long)2048*512, 2048, 512, 2048, B_, 1, &c0);
        GDesc dGo = mkDesc(PAo, 512, (long)512*512, PT2, 512, (long)512*512,
                           nullptr, T2, (long)512*512, nullptr, 0,
                           PAll, 1024, (long)512*1024, 512, 512, 512, B_, 1, &c1);
        launchPair(dGr, c0, dGo, c1);
    }
    // ---- pair 5: QKV (N=1536)  ||  Wf = Wp@We_top -> Wcat rows 512..1023 ----
    {
        GDesc dQKV = mkDesc(PGr, 512, 0, PWqkv, 1536, 0, bqkv, nullptr, 0,
                            QKV, 0, NONE, 0, 0, TOK, 1536, 512, 1, 0, &c0);
        GDesc dWf = mkDesc(PWp, 512, 0, PWe, 512, 0, nullptr, nullptr, 0,
                           nullptr, 0, PWcatBot, 512, 0, 512, 512, 512, 1, 0, &c1);
        launchPair(dQKV, c0, dWf, c1);
    }
    // ---- attention (writes permuted Om into pAll cols 512..1023) ----
    {
        dim3 grid(SEGS, H_, 2);
        attn_mean_kernel<<<grid, 128>>>(QKV, PAll.h, PAll.l);
    }
    // ---- final: out = [Go | Om_perm] @ [We_bot ; Wf] + b2 ----
    {
        GDesc dF = mkDesc(PAll, 1024, 0, PWcat, 512, 0, b2, nullptr, 0,
                          out, 0, NONE, 0, 0, OUT_ROWS, 512, 1024, 1, 0, &c0);
        launchOne(dF, c0);
    }
}